// round 2
// baseline (speedup 1.0000x reference)
#include <cuda_runtime.h>
#include <math.h>

#define B_    8
#define C_    128
#define Hh_   128
#define Ww_   128
#define N_    16384      // H*W
#define HEADS_ 8
#define CH_   16         // C/HEADS
#define HID_  340
#define HID2_ 680
#define C2_   256

// ---------------- static scratch (no allocations allowed) ----------------
__device__ float g_bufCa[(size_t)B_ * C_ * N_];
__device__ float g_bufCb[(size_t)B_ * C_ * N_];
__device__ float g_bufCc[(size_t)B_ * C_ * N_];
__device__ float g_buf2Ca[(size_t)B_ * C2_ * N_];
__device__ float g_buf2Cb[(size_t)B_ * C2_ * N_];
__device__ float g_bufHa[(size_t)B_ * HID2_ * N_];
__device__ float g_bufHb[(size_t)B_ * HID2_ * N_];
__device__ float g_normq[B_ * C_];
__device__ float g_normk[B_ * C_];
__device__ float g_attnw[B_ * HEADS_ * CH_ * CH_];
__device__ float g_pool[B_ * C_];
__device__ float g_cas[B_ * C_];

// ---------------- LayerNorm over channels per pixel ----------------
__global__ void lnk(const float* __restrict__ X, const float* __restrict__ w,
                    const float* __restrict__ bias, float* __restrict__ Y)
{
    int p = blockIdx.x * 256 + threadIdx.x;
    int b = blockIdx.y;
    const float* xb = X + (size_t)b * C_ * N_ + p;
    float s = 0.f, ss = 0.f;
    #pragma unroll 4
    for (int c = 0; c < C_; ++c) {
        float v = xb[(size_t)c * N_];
        s += v; ss += v * v;
    }
    float mu  = s * (1.f / C_);
    float var = ss * (1.f / C_) - mu * mu;
    float inv = rsqrtf(var + 1e-5f);
    float* yb = Y + (size_t)b * C_ * N_ + p;
    #pragma unroll 4
    for (int c = 0; c < C_; ++c) {
        float v = xb[(size_t)c * N_];
        yb[(size_t)c * N_] = (v - mu) * inv * w[c] + bias[c];
    }
}

// ---------------- generic SGEMM: Y[b, Yoff+o, p] = sum_c W[o,c] X[b,c,p] ----------------
__global__ void sgemm64(const float* __restrict__ Wm, const float* __restrict__ X,
                        float* __restrict__ Y, const float* __restrict__ R,
                        int Cout, int Cin, int XCtot, int YCtot, int Yoff,
                        int doResid, int doFinal)
{
    const int bz = blockIdx.z;
    const int o0 = blockIdx.y * 64;
    const int p0 = blockIdx.x * 64;
    const float* Xb = X + (size_t)bz * XCtot * N_;

    __shared__ float Ws[16][64];
    __shared__ float Xs[16][64];

    const int tid = threadIdx.x;
    const int tx = tid & 15, ty = tid >> 4;

    float acc[4][4];
    #pragma unroll
    for (int i = 0; i < 4; ++i)
        #pragma unroll
        for (int j = 0; j < 4; ++j) acc[i][j] = 0.f;

    int ktiles = (Cin + 15) >> 4;
    for (int kt = 0; kt < ktiles; ++kt) {
        int k0 = kt * 16;
        #pragma unroll
        for (int u = 0; u < 4; ++u) {
            int e = tid + 256 * u;
            int m = e & 63, k = e >> 6;
            int o = o0 + m, kk = k0 + k;
            Ws[k][m] = (o < Cout && kk < Cin) ? Wm[(size_t)o * Cin + kk] : 0.f;
        }
        #pragma unroll
        for (int u = 0; u < 4; ++u) {
            int e = tid + 256 * u;
            int n = e & 63, k = e >> 6;
            int kk = k0 + k;
            Xs[k][n] = (kk < Cin) ? Xb[(size_t)kk * N_ + p0 + n] : 0.f;
        }
        __syncthreads();
        #pragma unroll
        for (int k = 0; k < 16; ++k) {
            float a[4], bb[4];
            #pragma unroll
            for (int i = 0; i < 4; ++i) a[i] = Ws[k][ty * 4 + i];
            #pragma unroll
            for (int j = 0; j < 4; ++j) bb[j] = Xs[k][tx * 4 + j];
            #pragma unroll
            for (int i = 0; i < 4; ++i)
                #pragma unroll
                for (int j = 0; j < 4; ++j) acc[i][j] += a[i] * bb[j];
        }
        __syncthreads();
    }

    #pragma unroll
    for (int i = 0; i < 4; ++i) {
        int o = o0 + ty * 4 + i;
        if (o >= Cout) continue;
        #pragma unroll
        for (int j = 0; j < 4; ++j) {
            int p = p0 + tx * 4 + j;
            float v = acc[i][j];
            if (doResid) v += R[((size_t)bz * Cout + o) * N_ + p];
            if (doFinal) v = isfinite(v) ? v : 1e-5f;
            Y[((size_t)bz * YCtot + Yoff + o) * N_ + p] = v;
        }
    }
}

// ---------------- depthwise 3x3, SAME padding ----------------
__global__ void dwconv3k(const float* __restrict__ X, const float* __restrict__ Wd,
                         float* __restrict__ Y, int CHn)
{
    int p = blockIdx.x * 256 + threadIdx.x;
    int c = blockIdx.y, b = blockIdx.z;
    int y = p >> 7, x = p & 127;
    const float* xb = X + ((size_t)b * CHn + c) * N_;
    float w[9];
    #pragma unroll
    for (int t = 0; t < 9; ++t) w[t] = Wd[c * 9 + t];
    float s = 0.f;
    #pragma unroll
    for (int dy = -1; dy <= 1; ++dy) {
        int yy = y + dy;
        if (yy < 0 || yy >= Hh_) continue;
        #pragma unroll
        for (int dx = -1; dx <= 1; ++dx) {
            int xx = x + dx;
            if (xx < 0 || xx >= Ww_) continue;
            s += xb[yy * Ww_ + xx] * w[(dy + 1) * 3 + (dx + 1)];
        }
    }
    Y[((size_t)b * CHn + c) * N_ + p] = s;
}

// ---------------- per-(b,c) L2 norm over N ----------------
__global__ void rownormk(const float* __restrict__ X, float* __restrict__ nrm, int Ctot)
{
    int c = blockIdx.x, b = blockIdx.y;
    const float* xb = X + ((size_t)b * Ctot + c) * N_;
    float s = 0.f;
    for (int n = threadIdx.x; n < N_; n += 256) {
        float v = xb[n]; s += v * v;
    }
    __shared__ float red[256];
    red[threadIdx.x] = s; __syncthreads();
    for (int st = 128; st > 0; st >>= 1) {
        if (threadIdx.x < st) red[threadIdx.x] += red[threadIdx.x + st];
        __syncthreads();
    }
    if (threadIdx.x == 0) nrm[b * C_ + c] = fmaxf(sqrtf(red[0]), 1e-12f);
}

// ---------------- channel attention logits + softmax: [B,H,16,16] ----------------
__global__ void attnk(const float* __restrict__ Q, const float* __restrict__ KV,
                      const float* __restrict__ nq, const float* __restrict__ nk,
                      const float* __restrict__ temp, float* __restrict__ attnOut)
{
    int h = blockIdx.x, b = blockIdx.y;
    const float* qb = Q  + ((size_t)b * C_  + h * CH_) * N_;
    const float* kb = KV + ((size_t)b * C2_ + h * CH_) * N_;

    __shared__ float sm[16 * 16 * 16];   // 16KB; phase1: qs/ks, phase2: partials
    float* qs = sm;
    float* ks = sm + 1024;

    int tid = threadIdx.x;
    int i = tid & 15, s = tid >> 4;
    float acc[16];
    #pragma unroll
    for (int j = 0; j < 16; ++j) acc[j] = 0.f;

    for (int n0 = 0; n0 < N_; n0 += 64) {
        #pragma unroll
        for (int u = 0; u < 4; ++u) {
            int e = tid + 256 * u;
            int r = e >> 6, cc = e & 63;
            qs[r * 64 + cc] = qb[(size_t)r * N_ + n0 + cc];
            ks[r * 64 + cc] = kb[(size_t)r * N_ + n0 + cc];
        }
        __syncthreads();
        #pragma unroll
        for (int t = 0; t < 4; ++t) {
            float qv = qs[i * 64 + s * 4 + t];
            #pragma unroll
            for (int j = 0; j < 16; ++j) acc[j] += qv * ks[j * 64 + s * 4 + t];
        }
        __syncthreads();
    }
    #pragma unroll
    for (int j = 0; j < 16; ++j) sm[s * 256 + i * 16 + j] = acc[j];
    __syncthreads();

    int i2 = tid >> 4, j2 = tid & 15;
    float a = 0.f;
    #pragma unroll
    for (int s2 = 0; s2 < 16; ++s2) a += sm[s2 * 256 + i2 * 16 + j2];
    a = a / (nq[b * C_ + h * CH_ + i2] * nk[b * C_ + h * CH_ + j2]) * temp[h];

    unsigned mask = 0xFFFFFFFFu;
    float mx = a;
    for (int w = 8; w > 0; w >>= 1) mx = fmaxf(mx, __shfl_xor_sync(mask, mx, w, 16));
    float e = expf(a - mx);
    float ssum = e;
    for (int w = 8; w > 0; w >>= 1) ssum += __shfl_xor_sync(mask, ssum, w, 16);
    attnOut[(((size_t)b * HEADS_ + h) * 16 + i2) * 16 + j2] = e / ssum;
}

// ---------------- out = attn @ v ----------------
__global__ void attnvk(const float* __restrict__ attn, const float* __restrict__ KV,
                       float* __restrict__ Y)
{
    int h = blockIdx.y, b = blockIdx.z;
    int p = blockIdx.x * 256 + threadIdx.x;
    __shared__ float a[256];
    a[threadIdx.x] = attn[((size_t)(b * HEADS_ + h)) * 256 + threadIdx.x];
    __syncthreads();
    const float* vb = KV + ((size_t)b * C2_ + C_ + h * CH_) * N_ + p;
    float out[16];
    #pragma unroll
    for (int i = 0; i < 16; ++i) out[i] = 0.f;
    #pragma unroll
    for (int j = 0; j < 16; ++j) {
        float vv = vb[(size_t)j * N_];
        #pragma unroll
        for (int i = 0; i < 16; ++i) out[i] += a[i * 16 + j] * vv;
    }
    float* yb = Y + ((size_t)b * C_ + h * CH_) * N_ + p;
    #pragma unroll
    for (int i = 0; i < 16; ++i) yb[(size_t)i * N_] = out[i];
}

// ---------------- global average pool per (b,c) ----------------
__global__ void capoolk(const float* __restrict__ X, float* __restrict__ pool)
{
    int c = blockIdx.x, b = blockIdx.y;
    const float* xb = X + ((size_t)b * C_ + c) * N_;
    float s = 0.f;
    for (int n = threadIdx.x; n < N_; n += 256) s += xb[n];
    __shared__ float red[256];
    red[threadIdx.x] = s; __syncthreads();
    for (int st = 128; st > 0; st >>= 1) {
        if (threadIdx.x < st) red[threadIdx.x] += red[threadIdx.x + st];
        __syncthreads();
    }
    if (threadIdx.x == 0) pool[b * C_ + c] = red[0] * (1.f / N_);
}

// ---------------- CA: relu FC (128->8) + sigmoid FC (8->128) ----------------
__global__ void cafck(const float* __restrict__ pool,
                      const float* __restrict__ w1, const float* __restrict__ b1,
                      const float* __restrict__ w2, const float* __restrict__ b2,
                      float* __restrict__ cas)
{
    int b = blockIdx.x, t = threadIdx.x;
    __shared__ float pl[C_];
    __shared__ float hid[8];
    pl[t] = pool[b * C_ + t];
    __syncthreads();
    if (t < 8) {
        float s = b1[t];
        #pragma unroll 4
        for (int c = 0; c < C_; ++c) s += w1[t * C_ + c] * pl[c];
        hid[t] = fmaxf(s, 0.f);
    }
    __syncthreads();
    float s = b2[t];
    #pragma unroll
    for (int r = 0; r < 8; ++r) s += w2[t * 8 + r] * hid[r];
    cas[b * C_ + t] = 1.f / (1.f + expf(-s));
}

// ---------------- x_out = fuse * ca + origin ----------------
__global__ void scaleaddk(const float* __restrict__ fuse, const float* __restrict__ cas,
                          const float* __restrict__ origin, float* __restrict__ Y)
{
    size_t idx = (size_t)blockIdx.x * 256 + threadIdx.x;
    int b = (int)(idx / ((size_t)C_ * N_));
    int c = (int)((idx / N_) % C_);
    Y[idx] = fuse[idx] * cas[b * C_ + c] + origin[idx];
}

// ---------------- gated = gelu(x1) * x2 ----------------
__global__ void gelugatek(const float* __restrict__ h2, float* __restrict__ g)
{
    size_t idx = (size_t)blockIdx.x * 256 + threadIdx.x;
    size_t per = (size_t)HID_ * N_;
    int b = (int)(idx / per);
    size_t r = idx - (size_t)b * per;
    int hc = (int)(r / N_);
    int p  = (int)(r - (size_t)hc * N_);
    const float* base = h2 + (size_t)b * HID2_ * N_;
    float x1 = base[(size_t)hc * N_ + p];
    float x2 = base[(size_t)(hc + HID_) * N_ + p];
    float ge = 0.5f * x1 * (1.f + erff(x1 * 0.70710678118654752f));
    g[idx] = ge * x2;
}

// ---------------- host ----------------
extern "C" void kernel_launch(void* const* d_in, const int* in_sizes, int n_in,
                              void* d_out, int out_size)
{
    (void)in_sizes; (void)n_in; (void)out_size;
    const float* origin  = (const float*)d_in[0];
    const float* low     = (const float*)d_in[1];
    const float* high    = (const float*)d_in[2];
    const float* norm1_w = (const float*)d_in[3];
    const float* norm1_b = (const float*)d_in[4];
    const float* norm_1_w= (const float*)d_in[5];
    const float* norm_1_b= (const float*)d_in[6];
    const float* norm2_w = (const float*)d_in[7];
    const float* norm2_b = (const float*)d_in[8];
    const float* a1_q    = (const float*)d_in[9];
    const float* a1_qdw  = (const float*)d_in[10];
    const float* a1_kv   = (const float*)d_in[11];
    const float* a1_kvdw = (const float*)d_in[12];
    const float* a1_po   = (const float*)d_in[13];
    const float* a1_temp = (const float*)d_in[14];
    const float* a2_q    = (const float*)d_in[15];
    const float* a2_qdw  = (const float*)d_in[16];
    const float* a2_kv   = (const float*)d_in[17];
    const float* a2_kvdw = (const float*)d_in[18];
    const float* a2_po   = (const float*)d_in[19];
    const float* a2_temp = (const float*)d_in[20];
    const float* conv1_w = (const float*)d_in[21];
    const float* ca1_w   = (const float*)d_in[22];
    const float* ca1_b   = (const float*)d_in[23];
    const float* ca2_w   = (const float*)d_in[24];
    const float* ca2_b   = (const float*)d_in[25];
    const float* ffn_pi  = (const float*)d_in[26];
    const float* ffn_dw  = (const float*)d_in[27];
    const float* ffn_po  = (const float*)d_in[28];
    float* out = (float*)d_out;

    float *bufCa, *bufCb, *bufCc, *buf2Ca, *buf2Cb, *bufHa, *bufHb;
    float *nq, *nk, *attnw, *pool, *cas;
    cudaGetSymbolAddress((void**)&bufCa, g_bufCa);
    cudaGetSymbolAddress((void**)&bufCb, g_bufCb);
    cudaGetSymbolAddress((void**)&bufCc, g_bufCc);
    cudaGetSymbolAddress((void**)&buf2Ca, g_buf2Ca);
    cudaGetSymbolAddress((void**)&buf2Cb, g_buf2Cb);
    cudaGetSymbolAddress((void**)&bufHa, g_bufHa);
    cudaGetSymbolAddress((void**)&bufHb, g_bufHb);
    cudaGetSymbolAddress((void**)&nq, g_normq);
    cudaGetSymbolAddress((void**)&nk, g_normk);
    cudaGetSymbolAddress((void**)&attnw, g_attnw);
    cudaGetSymbolAddress((void**)&pool, g_pool);
    cudaGetSymbolAddress((void**)&cas, g_cas);

    dim3 tb(256);
    dim3 gLN(N_ / 256, B_);
    dim3 gGemmC(N_ / 64, C_ / 64, B_);        // Cout=128
    dim3 gGemm2C(N_ / 64, C2_ / 64, B_);      // Cout=256
    dim3 gGemmH(N_ / 64, (HID2_ + 63) / 64, B_);  // Cout=680
    dim3 gRow(C_, B_);
    dim3 gAttn(HEADS_, B_);
    dim3 gAV(N_ / 256, HEADS_, B_);

    // ===== path 1: x_low = low + attn(kv=LN(low), q=high) =====
    lnk<<<gLN, tb>>>(low, norm1_w, norm1_b, bufCa);
    sgemm64<<<gGemmC, tb>>>(a1_q, high, bufCb, nullptr, C_, C_, C_, C_, 0, 0, 0);
    dwconv3k<<<dim3(N_ / 256, C_, B_), tb>>>(bufCb, a1_qdw, bufCc, C_);
    sgemm64<<<gGemm2C, tb>>>(a1_kv, bufCa, buf2Ca, nullptr, C2_, C_, C_, C2_, 0, 0, 0);
    dwconv3k<<<dim3(N_ / 256, C2_, B_), tb>>>(buf2Ca, a1_kvdw, buf2Cb, C2_);
    rownormk<<<gRow, tb>>>(bufCc, nq, C_);
    rownormk<<<gRow, tb>>>(buf2Cb, nk, C2_);
    attnk<<<gAttn, tb>>>(bufCc, buf2Cb, nq, nk, a1_temp, attnw);
    attnvk<<<gAV, tb>>>(attnw, buf2Cb, bufCb);
    sgemm64<<<gGemmC, tb>>>(a1_po, bufCb, buf2Ca, low, C_, C_, C_, C2_, 0, 1, 0);

    // ===== path 2: x_high = high + attn(kv=LN(high), q=low) =====
    lnk<<<gLN, tb>>>(high, norm_1_w, norm_1_b, bufCa);
    sgemm64<<<gGemmC, tb>>>(a2_q, low, bufCb, nullptr, C_, C_, C_, C_, 0, 0, 0);
    dwconv3k<<<dim3(N_ / 256, C_, B_), tb>>>(bufCb, a2_qdw, bufCc, C_);
    sgemm64<<<gGemm2C, tb>>>(a2_kv, bufCa, buf2Cb, nullptr, C2_, C_, C_, C2_, 0, 0, 0);
    dwconv3k<<<dim3(N_ / 256, C2_, B_), tb>>>(buf2Cb, a2_kvdw, bufHa, C2_);  // bufHa as 2C scratch
    rownormk<<<gRow, tb>>>(bufCc, nq, C_);
    rownormk<<<gRow, tb>>>(bufHa, nk, C2_);
    attnk<<<gAttn, tb>>>(bufCc, bufHa, nq, nk, a2_temp, attnw);
    attnvk<<<gAV, tb>>>(attnw, bufHa, bufCb);
    sgemm64<<<gGemmC, tb>>>(a2_po, bufCb, buf2Ca, high, C_, C_, C_, C2_, C_, 1, 0);

    // ===== fuse: conv1(concat) -> CA -> + origin =====
    sgemm64<<<gGemmC, tb>>>(conv1_w, buf2Ca, bufCa, nullptr, C_, C2_, C2_, C_, 0, 0, 0);
    capoolk<<<gRow, tb>>>(bufCa, pool);
    cafck<<<dim3(B_), dim3(128)>>>(pool, ca1_w, ca1_b, ca2_w, ca2_b, cas);
    scaleaddk<<<dim3((unsigned)(((size_t)B_ * C_ * N_) / 256)), tb>>>(bufCa, cas, origin, bufCb);

    // ===== FFN with residual =====
    lnk<<<gLN, tb>>>(bufCb, norm2_w, norm2_b, bufCa);
    sgemm64<<<gGemmH, tb>>>(ffn_pi, bufCa, bufHa, nullptr, HID2_, C_, C_, HID2_, 0, 0, 0);
    dwconv3k<<<dim3(N_ / 256, HID2_, B_), tb>>>(bufHa, ffn_dw, bufHb, HID2_);
    gelugatek<<<dim3((unsigned)(((size_t)B_ * HID_ * N_) / 256)), tb>>>(bufHb, bufHa);
    sgemm64<<<gGemmC, tb>>>(ffn_po, bufHa, out, bufCb, C_, HID_, HID_, C_, 0, 1, 1);
}

// round 4
// speedup vs baseline: 1.2141x; 1.2141x over previous
#include <cuda_runtime.h>
#include <math.h>

#define B_    8
#define C_    128
#define Hh_   128
#define Ww_   128
#define N_    16384      // H*W
#define HEADS_ 8
#define CH_   16         // C/HEADS
#define HID_  340
#define HID2_ 680
#define C2_   256

// ---------------- static scratch (no allocations allowed) ----------------
__device__ float g_bufCa[(size_t)B_ * C_ * N_];
__device__ float g_bufCb[(size_t)B_ * C_ * N_];
__device__ float g_bufCc[(size_t)B_ * C_ * N_];
__device__ float g_buf2Ca[(size_t)B_ * C2_ * N_];
__device__ float g_buf2Cb[(size_t)B_ * C2_ * N_];
__device__ float g_bufHa[(size_t)B_ * HID2_ * N_];
__device__ float g_bufHb[(size_t)B_ * HID_ * N_];
__device__ float g_normq[B_ * C_];
__device__ float g_normk[B_ * C_];
__device__ float g_attnw[B_ * HEADS_ * CH_ * CH_];
__device__ float g_Mw[B_ * C_ * C_];
__device__ float g_pool[B_ * C_];
__device__ float g_cas[B_ * C_];

// ---------------- LayerNorm over channels per pixel ----------------
__global__ void lnk(const float* __restrict__ X, const float* __restrict__ w,
                    const float* __restrict__ bias, float* __restrict__ Y)
{
    int p = blockIdx.x * 256 + threadIdx.x;
    int b = blockIdx.y;
    const float* xb = X + (size_t)b * C_ * N_ + p;
    float s = 0.f, ss = 0.f;
    #pragma unroll 4
    for (int c = 0; c < C_; ++c) {
        float v = xb[(size_t)c * N_];
        s += v; ss += v * v;
    }
    float mu  = s * (1.f / C_);
    float var = ss * (1.f / C_) - mu * mu;
    float inv = rsqrtf(var + 1e-5f);
    float* yb = Y + (size_t)b * C_ * N_ + p;
    #pragma unroll 4
    for (int c = 0; c < C_; ++c) {
        float v = xb[(size_t)c * N_];
        yb[(size_t)c * N_] = (v - mu) * inv * w[c] + bias[c];
    }
}

// ---------------- SGEMM 128x128x16, 8x8 micro-tile ----------------
// Y[b, Yoff+o, p] = sum_c W[o,c] X[b,c,p]  (+resid, +nan_to_num)
__global__ void sgemm128(const float* __restrict__ Wm, const float* __restrict__ X,
                         float* __restrict__ Y, const float* __restrict__ R,
                         int Cout, int Cin, int XCtot, int YCtot, int Yoff,
                         int flags, int WstrideB)
{
    const int bz = blockIdx.z;
    const int o0 = blockIdx.y * 128;
    const int p0 = blockIdx.x * 128;
    const float* Wb = Wm + (size_t)bz * WstrideB;
    const float* Xb = X + (size_t)bz * XCtot * N_;

    __shared__ float Ws[16][128];
    __shared__ float Xs[16][128];

    const int tid = threadIdx.x;
    const int tx = tid & 15, ty = tid >> 4;

    float acc[8][8];
    #pragma unroll
    for (int i = 0; i < 8; ++i)
        #pragma unroll
        for (int j = 0; j < 8; ++j) acc[i][j] = 0.f;

    float wr[2][4];
    float4 xr[2];
    const int ktiles = (Cin + 15) >> 4;

    // ---- preload tile 0 into regs ----
    {
        #pragma unroll
        for (int u = 0; u < 2; ++u) {
            int e4 = tid + 256 * u;
            int row = e4 & 127, kq = e4 >> 7;
            int o = o0 + row;
            #pragma unroll
            for (int t = 0; t < 4; ++t) {
                int kk = kq * 4 + t;
                wr[u][t] = (o < Cout && kk < Cin) ? Wb[(size_t)o * Cin + kk] : 0.f;
            }
        }
        #pragma unroll
        for (int u = 0; u < 2; ++u) {
            int e = tid + 256 * u;
            int row = e >> 5, cq = e & 31;
            xr[u] = (row < Cin) ? *(const float4*)&Xb[(size_t)row * N_ + p0 + cq * 4]
                                : make_float4(0.f, 0.f, 0.f, 0.f);
        }
    }

    for (int kt = 0; kt < ktiles; ++kt) {
        // ---- store regs -> smem ----
        #pragma unroll
        for (int u = 0; u < 2; ++u) {
            int e4 = tid + 256 * u;
            int row = e4 & 127, kq = e4 >> 7;
            #pragma unroll
            for (int t = 0; t < 4; ++t) Ws[kq * 4 + t][row] = wr[u][t];
        }
        #pragma unroll
        for (int u = 0; u < 2; ++u) {
            int e = tid + 256 * u;
            int row = e >> 5, cq = e & 31;
            *(float4*)&Xs[row][cq * 4] = xr[u];
        }
        __syncthreads();

        // ---- prefetch next tile (overlaps compute) ----
        if (kt + 1 < ktiles) {
            int k0 = (kt + 1) * 16;
            #pragma unroll
            for (int u = 0; u < 2; ++u) {
                int e4 = tid + 256 * u;
                int row = e4 & 127, kq = e4 >> 7;
                int o = o0 + row;
                #pragma unroll
                for (int t = 0; t < 4; ++t) {
                    int kk = k0 + kq * 4 + t;
                    wr[u][t] = (o < Cout && kk < Cin) ? Wb[(size_t)o * Cin + kk] : 0.f;
                }
            }
            #pragma unroll
            for (int u = 0; u < 2; ++u) {
                int e = tid + 256 * u;
                int row = e >> 5, cq = e & 31;
                int kk = k0 + row;
                xr[u] = (kk < Cin) ? *(const float4*)&Xb[(size_t)kk * N_ + p0 + cq * 4]
                                   : make_float4(0.f, 0.f, 0.f, 0.f);
            }
        }

        // ---- compute ----
        #pragma unroll
        for (int k = 0; k < 16; ++k) {
            float4 a0 = *(const float4*)&Ws[k][ty * 8];
            float4 a1 = *(const float4*)&Ws[k][ty * 8 + 4];
            float4 b0 = *(const float4*)&Xs[k][tx * 8];
            float4 b1 = *(const float4*)&Xs[k][tx * 8 + 4];
            float av[8] = {a0.x, a0.y, a0.z, a0.w, a1.x, a1.y, a1.z, a1.w};
            float bv[8] = {b0.x, b0.y, b0.z, b0.w, b1.x, b1.y, b1.z, b1.w};
            #pragma unroll
            for (int i = 0; i < 8; ++i)
                #pragma unroll
                for (int j = 0; j < 8; ++j) acc[i][j] += av[i] * bv[j];
        }
        __syncthreads();
    }

    // ---- epilogue ----
    const int doResid = flags & 1, doFinal = flags & 2;
    #pragma unroll
    for (int i = 0; i < 8; ++i) {
        int o = o0 + ty * 8 + i;
        if (o >= Cout) continue;
        size_t ybase = ((size_t)bz * YCtot + Yoff + o) * N_ + p0 + tx * 8;
        float v[8];
        #pragma unroll
        for (int j = 0; j < 8; ++j) v[j] = acc[i][j];
        if (doResid) {
            size_t rbase = ((size_t)bz * Cout + o) * N_ + p0 + tx * 8;
            float4 r0 = *(const float4*)&R[rbase];
            float4 r1 = *(const float4*)&R[rbase + 4];
            v[0] += r0.x; v[1] += r0.y; v[2] += r0.z; v[3] += r0.w;
            v[4] += r1.x; v[5] += r1.y; v[6] += r1.z; v[7] += r1.w;
        }
        if (doFinal) {
            #pragma unroll
            for (int j = 0; j < 8; ++j) v[j] = isfinite(v[j]) ? v[j] : 1e-5f;
        }
        float4 s0 = make_float4(v[0], v[1], v[2], v[3]);
        float4 s1 = make_float4(v[4], v[5], v[6], v[7]);
        *(float4*)&Y[ybase] = s0;
        *(float4*)&Y[ybase + 4] = s1;
    }
}

// ---------------- depthwise 3x3, SAME padding ----------------
__global__ void dwconv3k(const float* __restrict__ X, const float* __restrict__ Wd,
                         float* __restrict__ Y, int CHn)
{
    int p = blockIdx.x * 256 + threadIdx.x;
    int c = blockIdx.y, b = blockIdx.z;
    int y = p >> 7, x = p & 127;
    const float* xb = X + ((size_t)b * CHn + c) * N_;
    float w[9];
    #pragma unroll
    for (int t = 0; t < 9; ++t) w[t] = Wd[c * 9 + t];
    float s = 0.f;
    #pragma unroll
    for (int dy = -1; dy <= 1; ++dy) {
        int yy = y + dy;
        if (yy < 0 || yy >= Hh_) continue;
        #pragma unroll
        for (int dx = -1; dx <= 1; ++dx) {
            int xx = x + dx;
            if (xx < 0 || xx >= Ww_) continue;
            s += xb[yy * Ww_ + xx] * w[(dy + 1) * 3 + (dx + 1)];
        }
    }
    Y[((size_t)b * CHn + c) * N_ + p] = s;
}

// ---------------- fused FFN dwconv(680) + gelu-gate -> 340 ----------------
__global__ void dwgatek(const float* __restrict__ X, const float* __restrict__ Wd,
                        float* __restrict__ Y)
{
    int p = blockIdx.x * 256 + threadIdx.x;
    int c = blockIdx.y, b = blockIdx.z;
    int y = p >> 7, x = p & 127;
    const float* x1b = X + ((size_t)b * HID2_ + c) * N_;
    const float* x2b = X + ((size_t)b * HID2_ + c + HID_) * N_;
    float w1[9], w2[9];
    #pragma unroll
    for (int t = 0; t < 9; ++t) { w1[t] = Wd[c * 9 + t]; w2[t] = Wd[(c + HID_) * 9 + t]; }
    float s1 = 0.f, s2 = 0.f;
    #pragma unroll
    for (int dy = -1; dy <= 1; ++dy) {
        int yy = y + dy;
        if (yy < 0 || yy >= Hh_) continue;
        #pragma unroll
        for (int dx = -1; dx <= 1; ++dx) {
            int xx = x + dx;
            if (xx < 0 || xx >= Ww_) continue;
            int off = yy * Ww_ + xx, t = (dy + 1) * 3 + (dx + 1);
            s1 += x1b[off] * w1[t];
            s2 += x2b[off] * w2[t];
        }
    }
    float ge = 0.5f * s1 * (1.f + erff(s1 * 0.70710678118654752f));
    Y[((size_t)b * HID_ + c) * N_ + p] = ge * s2;
}

// ---------------- per-(b,c) L2 norm over N ----------------
__global__ void rownormk(const float* __restrict__ X, float* __restrict__ nrm, int Ctot)
{
    int c = blockIdx.x, b = blockIdx.y;
    const float* xb = X + ((size_t)b * Ctot + c) * N_;
    float s = 0.f;
    for (int n = threadIdx.x; n < N_; n += 256) {
        float v = xb[n]; s += v * v;
    }
    __shared__ float red[256];
    red[threadIdx.x] = s; __syncthreads();
    for (int st = 128; st > 0; st >>= 1) {
        if (threadIdx.x < st) red[threadIdx.x] += red[threadIdx.x + st];
        __syncthreads();
    }
    if (threadIdx.x == 0) nrm[b * C_ + c] = fmaxf(sqrtf(red[0]), 1e-12f);
}

// ---------------- channel attention logits + softmax: [B,H,16,16] ----------------
__global__ void attnk(const float* __restrict__ Q, const float* __restrict__ KV,
                      const float* __restrict__ nq, const float* __restrict__ nk,
                      const float* __restrict__ temp, float* __restrict__ attnOut)
{
    int h = blockIdx.x, b = blockIdx.y;
    const float* qb = Q  + ((size_t)b * C_  + h * CH_) * N_;
    const float* kb = KV + ((size_t)b * C2_ + h * CH_) * N_;

    __shared__ float sm[16 * 16 * 16];
    float* qs = sm;
    float* ks = sm + 1024;

    int tid = threadIdx.x;
    int i = tid & 15, s = tid >> 4;
    float acc[16];
    #pragma unroll
    for (int j = 0; j < 16; ++j) acc[j] = 0.f;

    for (int n0 = 0; n0 < N_; n0 += 64) {
        #pragma unroll
        for (int u = 0; u < 4; ++u) {
            int e = tid + 256 * u;
            int r = e >> 6, cc = e & 63;
            qs[r * 64 + cc] = qb[(size_t)r * N_ + n0 + cc];
            ks[r * 64 + cc] = kb[(size_t)r * N_ + n0 + cc];
        }
        __syncthreads();
        #pragma unroll
        for (int t = 0; t < 4; ++t) {
            float qv = qs[i * 64 + s * 4 + t];
            #pragma unroll
            for (int j = 0; j < 16; ++j) acc[j] += qv * ks[j * 64 + s * 4 + t];
        }
        __syncthreads();
    }
    #pragma unroll
    for (int j = 0; j < 16; ++j) sm[s * 256 + i * 16 + j] = acc[j];
    __syncthreads();

    int i2 = tid >> 4, j2 = tid & 15;
    float a = 0.f;
    #pragma unroll
    for (int s2 = 0; s2 < 16; ++s2) a += sm[s2 * 256 + i2 * 16 + j2];
    a = a / (nq[b * C_ + h * CH_ + i2] * nk[b * C_ + h * CH_ + j2]) * temp[h];

    unsigned mask = 0xFFFFFFFFu;
    float mx = a;
    for (int w = 8; w > 0; w >>= 1) mx = fmaxf(mx, __shfl_xor_sync(mask, mx, w, 16));
    float e = expf(a - mx);
    float ssum = e;
    for (int w = 8; w > 0; w >>= 1) ssum += __shfl_xor_sync(mask, ssum, w, 16);
    attnOut[(((size_t)b * HEADS_ + h) * 16 + i2) * 16 + j2] = e / ssum;
}

// ---------------- M[b] = po @ blockdiag(attn[b]) : [C_, C_] ----------------
__global__ void poattnk(const float* __restrict__ po, const float* __restrict__ attn,
                        float* __restrict__ M)
{
    int b = blockIdx.x;
    __shared__ float at[HEADS_ * 256];
    for (int i = threadIdx.x; i < HEADS_ * 256; i += 256) at[i] = attn[(size_t)b * HEADS_ * 256 + i];
    __syncthreads();
    for (int idx = threadIdx.x; idx < C_ * C_; idx += 256) {
        int o = idx >> 7, cj = idx & 127;
        int h = cj >> 4, j = cj & 15;
        float s = 0.f;
        #pragma unroll
        for (int i = 0; i < 16; ++i) s += po[o * C_ + h * 16 + i] * at[h * 256 + i * 16 + j];
        M[((size_t)b * C_ + o) * C_ + cj] = s;
    }
}

// ---------------- global average pool per (b,c) ----------------
__global__ void capoolk(const float* __restrict__ X, float* __restrict__ pool)
{
    int c = blockIdx.x, b = blockIdx.y;
    const float* xb = X + ((size_t)b * C_ + c) * N_;
    float s = 0.f;
    for (int n = threadIdx.x; n < N_; n += 256) s += xb[n];
    __shared__ float red[256];
    red[threadIdx.x] = s; __syncthreads();
    for (int st = 128; st > 0; st >>= 1) {
        if (threadIdx.x < st) red[threadIdx.x] += red[threadIdx.x + st];
        __syncthreads();
    }
    if (threadIdx.x == 0) pool[b * C_ + c] = red[0] * (1.f / N_);
}

// ---------------- CA: relu FC (128->8) + sigmoid FC (8->128) ----------------
__global__ void cafck(const float* __restrict__ pool,
                      const float* __restrict__ w1, const float* __restrict__ b1,
                      const float* __restrict__ w2, const float* __restrict__ b2,
                      float* __restrict__ cas)
{
    int b = blockIdx.x, t = threadIdx.x;
    __shared__ float pl[C_];
    __shared__ float hid[8];
    pl[t] = pool[b * C_ + t];
    __syncthreads();
    if (t < 8) {
        float s = b1[t];
        #pragma unroll 4
        for (int c = 0; c < C_; ++c) s += w1[t * C_ + c] * pl[c];
        hid[t] = fmaxf(s, 0.f);
    }
    __syncthreads();
    float s = b2[t];
    #pragma unroll
    for (int r = 0; r < 8; ++r) s += w2[t * 8 + r] * hid[r];
    cas[b * C_ + t] = 1.f / (1.f + expf(-s));
}

// ---------------- x_out = fuse * ca + origin ----------------
__global__ void scaleaddk(const float* __restrict__ fuse, const float* __restrict__ cas,
                          const float* __restrict__ origin, float* __restrict__ Y)
{
    size_t idx = (size_t)blockIdx.x * 256 + threadIdx.x;
    int b = (int)(idx / ((size_t)C_ * N_));
    int c = (int)((idx / N_) % C_);
    Y[idx] = fuse[idx] * cas[b * C_ + c] + origin[idx];
}

// ---------------- host ----------------
extern "C" void kernel_launch(void* const* d_in, const int* in_sizes, int n_in,
                              void* d_out, int out_size)
{
    (void)in_sizes; (void)n_in; (void)out_size;
    const float* origin  = (const float*)d_in[0];
    const float* low     = (const float*)d_in[1];
    const float* high    = (const float*)d_in[2];
    const float* norm1_w = (const float*)d_in[3];
    const float* norm1_b = (const float*)d_in[4];
    const float* norm_1_w= (const float*)d_in[5];
    const float* norm_1_b= (const float*)d_in[6];
    const float* norm2_w = (const float*)d_in[7];
    const float* norm2_b = (const float*)d_in[8];
    const float* a1_q    = (const float*)d_in[9];
    const float* a1_qdw  = (const float*)d_in[10];
    const float* a1_kv   = (const float*)d_in[11];
    const float* a1_kvdw = (const float*)d_in[12];
    const float* a1_po   = (const float*)d_in[13];
    const float* a1_temp = (const float*)d_in[14];
    const float* a2_q    = (const float*)d_in[15];
    const float* a2_qdw  = (const float*)d_in[16];
    const float* a2_kv   = (const float*)d_in[17];
    const float* a2_kvdw = (const float*)d_in[18];
    const float* a2_po   = (const float*)d_in[19];
    const float* a2_temp = (const float*)d_in[20];
    const float* conv1_w = (const float*)d_in[21];
    const float* ca1_w   = (const float*)d_in[22];
    const float* ca1_b   = (const float*)d_in[23];
    const float* ca2_w   = (const float*)d_in[24];
    const float* ca2_b   = (const float*)d_in[25];
    const float* ffn_pi  = (const float*)d_in[26];
    const float* ffn_dw  = (const float*)d_in[27];
    const float* ffn_po  = (const float*)d_in[28];
    float* out = (float*)d_out;

    float *bufCa, *bufCb, *bufCc, *buf2Ca, *buf2Cb, *bufHa, *bufHb;
    float *nq, *nk, *attnw, *Mw, *pool, *cas;
    cudaGetSymbolAddress((void**)&bufCa, g_bufCa);
    cudaGetSymbolAddress((void**)&bufCb, g_bufCb);
    cudaGetSymbolAddress((void**)&bufCc, g_bufCc);
    cudaGetSymbolAddress((void**)&buf2Ca, g_buf2Ca);
    cudaGetSymbolAddress((void**)&buf2Cb, g_buf2Cb);
    cudaGetSymbolAddress((void**)&bufHa, g_bufHa);
    cudaGetSymbolAddress((void**)&bufHb, g_bufHb);
    cudaGetSymbolAddress((void**)&nq, g_normq);
    cudaGetSymbolAddress((void**)&nk, g_normk);
    cudaGetSymbolAddress((void**)&attnw, g_attnw);
    cudaGetSymbolAddress((void**)&Mw, g_Mw);
    cudaGetSymbolAddress((void**)&pool, g_pool);
    cudaGetSymbolAddress((void**)&cas, g_cas);

    dim3 tb(256);
    dim3 gLN(N_ / 256, B_);
    dim3 gG_C(N_ / 128, 1, B_);
    dim3 gG_2C(N_ / 128, 2, B_);
    dim3 gG_H(N_ / 128, (HID2_ + 127) / 128, B_);
    dim3 gRow(C_, B_);
    dim3 gAttn(HEADS_, B_);

    // ===== path 1: x_low = low + attn(kv=LN(low), q=high) =====
    lnk<<<gLN, tb>>>(low, norm1_w, norm1_b, bufCa);
    sgemm128<<<gG_C, tb>>>(a1_q, high, bufCb, nullptr, C_, C_, C_, C_, 0, 0, 0);
    dwconv3k<<<dim3(N_ / 256, C_, B_), tb>>>(bufCb, a1_qdw, bufCc, C_);
    sgemm128<<<gG_2C, tb>>>(a1_kv, bufCa, buf2Ca, nullptr, C2_, C_, C_, C2_, 0, 0, 0);
    dwconv3k<<<dim3(N_ / 256, C2_, B_), tb>>>(buf2Ca, a1_kvdw, buf2Cb, C2_);
    rownormk<<<gRow, tb>>>(bufCc, nq, C_);
    rownormk<<<gRow, tb>>>(buf2Cb, nk, C2_);
    attnk<<<gAttn, tb>>>(bufCc, buf2Cb, nq, nk, a1_temp, attnw);
    poattnk<<<dim3(B_), tb>>>(a1_po, attnw, Mw);
    // Y[:,0:C] = M_b @ v + low   (v = KV[C:2C])
    sgemm128<<<gG_C, tb>>>(Mw, buf2Cb + (size_t)C_ * N_, buf2Ca, low,
                           C_, C_, C2_, C2_, 0, 1, C_ * C_);

    // ===== path 2: x_high = high + attn(kv=LN(high), q=low) =====
    lnk<<<gLN, tb>>>(high, norm_1_w, norm_1_b, bufCa);
    sgemm128<<<gG_C, tb>>>(a2_q, low, bufCb, nullptr, C_, C_, C_, C_, 0, 0, 0);
    dwconv3k<<<dim3(N_ / 256, C_, B_), tb>>>(bufCb, a2_qdw, bufCc, C_);
    sgemm128<<<gG_2C, tb>>>(a2_kv, bufCa, buf2Cb, nullptr, C2_, C_, C_, C2_, 0, 0, 0);
    dwconv3k<<<dim3(N_ / 256, C2_, B_), tb>>>(buf2Cb, a2_kvdw, bufHa, C2_); // bufHa as 2C scratch
    rownormk<<<gRow, tb>>>(bufCc, nq, C_);
    rownormk<<<gRow, tb>>>(bufHa, nk, C2_);
    attnk<<<gAttn, tb>>>(bufCc, bufHa, nq, nk, a2_temp, attnw);
    poattnk<<<dim3(B_), tb>>>(a2_po, attnw, Mw);
    // Y[:,C:2C] = M_b @ v + high
    sgemm128<<<gG_C, tb>>>(Mw, bufHa + (size_t)C_ * N_, buf2Ca, high,
                           C_, C_, C2_, C2_, C_, 1, C_ * C_);

    // ===== fuse: conv1(concat) -> CA -> + origin =====
    sgemm128<<<gG_C, tb>>>(conv1_w, buf2Ca, bufCa, nullptr, C_, C2_, C2_, C_, 0, 0, 0);
    capoolk<<<gRow, tb>>>(bufCa, pool);
    cafck<<<dim3(B_), dim3(128)>>>(pool, ca1_w, ca1_b, ca2_w, ca2_b, cas);
    scaleaddk<<<dim3((unsigned)(((size_t)B_ * C_ * N_) / 256)), tb>>>(bufCa, cas, origin, bufCb);

    // ===== FFN with residual =====
    lnk<<<gLN, tb>>>(bufCb, norm2_w, norm2_b, bufCa);
    sgemm128<<<gG_H, tb>>>(ffn_pi, bufCa, bufHa, nullptr, HID2_, C_, C_, HID2_, 0, 0, 0);
    dwgatek<<<dim3(N_ / 256, HID_, B_), tb>>>(bufHa, ffn_dw, bufHb);
    sgemm128<<<gG_C, tb>>>(ffn_po, bufHb, out, bufCb, C_, HID_, HID_, C_, 0, 3, 0);
}

// round 5
// speedup vs baseline: 1.3645x; 1.1238x over previous
#include <cuda_runtime.h>
#include <math.h>

#define B_    8
#define C_    128
#define Hh_   128
#define Ww_   128
#define N_    16384      // H*W
#define HEADS_ 8
#define CH_   16         // C/HEADS
#define HID_  340
#define HID2_ 680
#define C2_   256

// ---------------- static scratch (no allocations allowed) ----------------
__device__ float g_bufCa[(size_t)B_ * C_ * N_];
__device__ float g_bufCb[(size_t)B_ * C_ * N_];
__device__ float g_bufCc[(size_t)B_ * C_ * N_];
__device__ float g_buf2Ca[(size_t)B_ * C2_ * N_];
__device__ float g_buf2Cb[(size_t)B_ * C2_ * N_];
__device__ float g_bufHa[(size_t)B_ * HID2_ * N_];
__device__ float g_bufHb[(size_t)B_ * HID_ * N_];
__device__ float g_attnw[B_ * HEADS_ * CH_ * CH_];
__device__ float g_Mw[B_ * C_ * C_];
__device__ float g_pool[B_ * C_];
__device__ float g_cas[B_ * C_];

// packed f32x2 helpers (Blackwell FFMA2 — PTX-only)
#define PK2(d, a)    asm("mov.b64 %0, {%1, %1};" : "=l"(d) : "f"(a))
#define FMA2(d, a, b) asm("fma.rn.f32x2 %0, %1, %2, %0;" : "+l"(d) : "l"(a), "l"(b))
#define UNPK2(lo, hi, s) asm("mov.b64 {%0, %1}, %2;" : "=f"(lo), "=f"(hi) : "l"(s))

// ---------------- LayerNorm over channels per pixel ----------------
__global__ void lnk(const float* __restrict__ X, const float* __restrict__ w,
                    const float* __restrict__ bias, float* __restrict__ Y)
{
    int p = blockIdx.x * 256 + threadIdx.x;
    int b = blockIdx.y;
    const float* xb = X + (size_t)b * C_ * N_ + p;
    float s = 0.f, ss = 0.f;
    #pragma unroll 4
    for (int c = 0; c < C_; ++c) {
        float v = xb[(size_t)c * N_];
        s += v; ss += v * v;
    }
    float mu  = s * (1.f / C_);
    float var = ss * (1.f / C_) - mu * mu;
    float inv = rsqrtf(var + 1e-5f);
    float* yb = Y + (size_t)b * C_ * N_ + p;
    #pragma unroll 4
    for (int c = 0; c < C_; ++c) {
        float v = xb[(size_t)c * N_];
        yb[(size_t)c * N_] = (v - mu) * inv * w[c] + bias[c];
    }
}

// ---------------- SGEMM 128x128x16, 8x8 micro-tile, f32x2 packed, double-buffered ----------------
// Y[b, Yoff+o, p] = sum_c W[o,c] X[b,c,p]  (+resid, +nan_to_num)
__global__ void __launch_bounds__(256, 2)
sgemm128(const float* __restrict__ Wm, const float* __restrict__ X,
         float* __restrict__ Y, const float* __restrict__ R,
         int Cout, int Cin, int XCtot, int YCtot, int Yoff,
         int flags, int WstrideB)
{
    const int bz = blockIdx.z;
    const int o0 = blockIdx.y * 128;
    const int p0 = blockIdx.x * 128;
    const float* Wb = Wm + (size_t)bz * WstrideB;
    const float* Xb = X + (size_t)bz * XCtot * N_;

    __shared__ __align__(16) float Ws[2][16][128];
    __shared__ __align__(16) float Xs[2][16][128];

    const int tid = threadIdx.x;
    const int tx = tid & 15, ty = tid >> 4;

    unsigned long long acc2[8][4];
    #pragma unroll
    for (int i = 0; i < 8; ++i)
        #pragma unroll
        for (int j = 0; j < 4; ++j) acc2[i][j] = 0ULL;

    float wr[2][4];
    float4 xr[2];
    const int ktiles = (Cin + 15) >> 4;

    // ---- preload tile 0 into regs ----
    {
        #pragma unroll
        for (int u = 0; u < 2; ++u) {
            int e4 = tid + 256 * u;
            int row = e4 & 127, kq = e4 >> 7;
            int o = o0 + row;
            #pragma unroll
            for (int t = 0; t < 4; ++t) {
                int kk = kq * 4 + t;
                wr[u][t] = (o < Cout && kk < Cin) ? Wb[(size_t)o * Cin + kk] : 0.f;
            }
        }
        #pragma unroll
        for (int u = 0; u < 2; ++u) {
            int e = tid + 256 * u;
            int row = e >> 5, cq = e & 31;
            xr[u] = (row < Cin) ? *(const float4*)&Xb[(size_t)row * N_ + p0 + cq * 4]
                                : make_float4(0.f, 0.f, 0.f, 0.f);
        }
    }

    int buf = 0;
    for (int kt = 0; kt < ktiles; ++kt) {
        // ---- store regs -> smem[buf] ----
        #pragma unroll
        for (int u = 0; u < 2; ++u) {
            int e4 = tid + 256 * u;
            int row = e4 & 127, kq = e4 >> 7;
            #pragma unroll
            for (int t = 0; t < 4; ++t) Ws[buf][kq * 4 + t][row] = wr[u][t];
        }
        #pragma unroll
        for (int u = 0; u < 2; ++u) {
            int e = tid + 256 * u;
            int row = e >> 5, cq = e & 31;
            *(float4*)&Xs[buf][row][cq * 4] = xr[u];
        }
        __syncthreads();

        // ---- prefetch next tile (overlaps compute) ----
        if (kt + 1 < ktiles) {
            int k0 = (kt + 1) * 16;
            #pragma unroll
            for (int u = 0; u < 2; ++u) {
                int e4 = tid + 256 * u;
                int row = e4 & 127, kq = e4 >> 7;
                int o = o0 + row;
                #pragma unroll
                for (int t = 0; t < 4; ++t) {
                    int kk = k0 + kq * 4 + t;
                    wr[u][t] = (o < Cout && kk < Cin) ? Wb[(size_t)o * Cin + kk] : 0.f;
                }
            }
            #pragma unroll
            for (int u = 0; u < 2; ++u) {
                int e = tid + 256 * u;
                int row = e >> 5, cq = e & 31;
                int kk = k0 + row;
                xr[u] = (kk < Cin) ? *(const float4*)&Xb[(size_t)kk * N_ + p0 + cq * 4]
                                   : make_float4(0.f, 0.f, 0.f, 0.f);
            }
        }

        // ---- compute (packed f32x2) ----
        #pragma unroll
        for (int k = 0; k < 16; ++k) {
            ulonglong2 q0 = *(const ulonglong2*)&Xs[buf][k][tx * 8];
            ulonglong2 q1 = *(const ulonglong2*)&Xs[buf][k][tx * 8 + 4];
            unsigned long long bb0 = q0.x, bb1 = q0.y, bb2 = q1.x, bb3 = q1.y;
            #pragma unroll
            for (int i = 0; i < 8; ++i) {
                unsigned long long ap;
                PK2(ap, Ws[buf][k][ty * 8 + i]);
                FMA2(acc2[i][0], ap, bb0);
                FMA2(acc2[i][1], ap, bb1);
                FMA2(acc2[i][2], ap, bb2);
                FMA2(acc2[i][3], ap, bb3);
            }
        }
        buf ^= 1;
    }

    // ---- epilogue ----
    const int doResid = flags & 1, doFinal = flags & 2;
    #pragma unroll
    for (int i = 0; i < 8; ++i) {
        int o = o0 + ty * 8 + i;
        if (o >= Cout) continue;
        size_t ybase = ((size_t)bz * YCtot + Yoff + o) * N_ + p0 + tx * 8;
        float v[8];
        #pragma unroll
        for (int j = 0; j < 4; ++j) UNPK2(v[2 * j], v[2 * j + 1], acc2[i][j]);
        if (doResid) {
            size_t rbase = ((size_t)bz * Cout + o) * N_ + p0 + tx * 8;
            float4 r0 = *(const float4*)&R[rbase];
            float4 r1 = *(const float4*)&R[rbase + 4];
            v[0] += r0.x; v[1] += r0.y; v[2] += r0.z; v[3] += r0.w;
            v[4] += r1.x; v[5] += r1.y; v[6] += r1.z; v[7] += r1.w;
        }
        if (doFinal) {
            #pragma unroll
            for (int j = 0; j < 8; ++j) v[j] = isfinite(v[j]) ? v[j] : 1e-5f;
        }
        *(float4*)&Y[ybase]     = make_float4(v[0], v[1], v[2], v[3]);
        *(float4*)&Y[ybase + 4] = make_float4(v[4], v[5], v[6], v[7]);
    }
}

// ---------------- depthwise 3x3, SAME padding (smem-tiled, 8 rows/block) ----------------
__global__ void dwconv3k(const float* __restrict__ X, const float* __restrict__ Wd,
                         float* __restrict__ Y, int CHn)
{
    int c = blockIdx.y, b = blockIdx.z;
    int y0 = blockIdx.x * 8;
    int tid = threadIdx.x;
    const float* xb = X + ((size_t)b * CHn + c) * N_;
    __shared__ float t[10][128];
    for (int i = tid; i < 320; i += 256) {
        int r = i >> 5, xq = i & 31;
        int yy = y0 - 1 + r;
        float4 v = make_float4(0.f, 0.f, 0.f, 0.f);
        if (yy >= 0 && yy < Hh_) v = *(const float4*)&xb[yy * 128 + xq * 4];
        *(float4*)&t[r][xq * 4] = v;
    }
    float w[9];
    #pragma unroll
    for (int q = 0; q < 9; ++q) w[q] = Wd[c * 9 + q];
    __syncthreads();
    int r = tid >> 5;
    int lx = tid & 31;
    float* yo = Y + ((size_t)b * CHn + c) * N_ + (y0 + r) * 128;
    #pragma unroll
    for (int u = 0; u < 4; ++u) {
        int x = u * 32 + lx;
        float s = 0.f;
        #pragma unroll
        for (int dy = 0; dy < 3; ++dy) {
            const float* row = t[r + dy];
            float m  = row[x];
            float l  = (x > 0)   ? row[x - 1] : 0.f;
            float rr = (x < 127) ? row[x + 1] : 0.f;
            s += l * w[dy * 3] + m * w[dy * 3 + 1] + rr * w[dy * 3 + 2];
        }
        yo[x] = s;
    }
}

// ---------------- fused FFN dwconv(680) + gelu-gate -> 340 (smem-tiled) ----------------
__global__ void dwgatek(const float* __restrict__ X, const float* __restrict__ Wd,
                        float* __restrict__ Y)
{
    int c = blockIdx.y, b = blockIdx.z;
    int y0 = blockIdx.x * 8;
    int tid = threadIdx.x;
    const float* x1b = X + ((size_t)b * HID2_ + c) * N_;
    const float* x2b = X + ((size_t)b * HID2_ + c + HID_) * N_;
    __shared__ float t1[10][128];
    __shared__ float t2[10][128];
    for (int i = tid; i < 320; i += 256) {
        int r = i >> 5, xq = i & 31;
        int yy = y0 - 1 + r;
        float4 v1 = make_float4(0.f, 0.f, 0.f, 0.f);
        float4 v2 = v1;
        if (yy >= 0 && yy < Hh_) {
            v1 = *(const float4*)&x1b[yy * 128 + xq * 4];
            v2 = *(const float4*)&x2b[yy * 128 + xq * 4];
        }
        *(float4*)&t1[r][xq * 4] = v1;
        *(float4*)&t2[r][xq * 4] = v2;
    }
    float w1[9], w2[9];
    #pragma unroll
    for (int q = 0; q < 9; ++q) { w1[q] = Wd[c * 9 + q]; w2[q] = Wd[(c + HID_) * 9 + q]; }
    __syncthreads();
    int r = tid >> 5;
    int lx = tid & 31;
    float* yo = Y + ((size_t)b * HID_ + c) * N_ + (y0 + r) * 128;
    #pragma unroll
    for (int u = 0; u < 4; ++u) {
        int x = u * 32 + lx;
        float s1 = 0.f, s2 = 0.f;
        #pragma unroll
        for (int dy = 0; dy < 3; ++dy) {
            const float* r1 = t1[r + dy];
            const float* r2 = t2[r + dy];
            float m1  = r1[x],  m2  = r2[x];
            float l1  = (x > 0)   ? r1[x - 1] : 0.f;
            float l2  = (x > 0)   ? r2[x - 1] : 0.f;
            float rr1 = (x < 127) ? r1[x + 1] : 0.f;
            float rr2 = (x < 127) ? r2[x + 1] : 0.f;
            s1 += l1 * w1[dy * 3] + m1 * w1[dy * 3 + 1] + rr1 * w1[dy * 3 + 2];
            s2 += l2 * w2[dy * 3] + m2 * w2[dy * 3 + 1] + rr2 * w2[dy * 3 + 2];
        }
        float ge = 0.5f * s1 * (1.f + erff(s1 * 0.70710678118654752f));
        yo[x] = ge * s2;
    }
}

// ---------------- channel attention logits + norms + softmax: [B,H,16,16] ----------------
__global__ void attnk(const float* __restrict__ Q, const float* __restrict__ KV,
                      const float* __restrict__ temp, float* __restrict__ attnOut)
{
    int h = blockIdx.x, b = blockIdx.y;
    const float* qb = Q  + ((size_t)b * C_  + h * CH_) * N_;
    const float* kb = KV + ((size_t)b * C2_ + h * CH_) * N_;

    __shared__ float sm[16 * 16 * 16];
    __shared__ float qqp[256], kkp[256];
    __shared__ float qqs[16], kks[16];
    float* qs = sm;
    float* ks = sm + 1024;

    int tid = threadIdx.x;
    int i = tid & 15, s = tid >> 4;
    float acc[16];
    #pragma unroll
    for (int j = 0; j < 16; ++j) acc[j] = 0.f;
    float qq = 0.f, kk = 0.f;

    for (int n0 = 0; n0 < N_; n0 += 64) {
        #pragma unroll
        for (int u = 0; u < 4; ++u) {
            int e = tid + 256 * u;
            int r = e >> 6, cc = e & 63;
            qs[r * 64 + cc] = qb[(size_t)r * N_ + n0 + cc];
            ks[r * 64 + cc] = kb[(size_t)r * N_ + n0 + cc];
        }
        __syncthreads();
        #pragma unroll
        for (int t = 0; t < 4; ++t) {
            float qv = qs[i * 64 + s * 4 + t];
            float kv = ks[i * 64 + s * 4 + t];
            qq += qv * qv;
            kk += kv * kv;
            #pragma unroll
            for (int j = 0; j < 16; ++j) acc[j] += qv * ks[j * 64 + s * 4 + t];
        }
        __syncthreads();
    }
    qqp[s * 16 + i] = qq;
    kkp[s * 16 + i] = kk;
    #pragma unroll
    for (int j = 0; j < 16; ++j) sm[s * 256 + i * 16 + j] = acc[j];
    __syncthreads();

    if (tid < 16) {
        float t0 = 0.f;
        #pragma unroll
        for (int s2 = 0; s2 < 16; ++s2) t0 += qqp[s2 * 16 + tid];
        qqs[tid] = fmaxf(sqrtf(t0), 1e-12f);
    } else if (tid < 32) {
        int j = tid - 16;
        float t0 = 0.f;
        #pragma unroll
        for (int s2 = 0; s2 < 16; ++s2) t0 += kkp[s2 * 16 + j];
        kks[j] = fmaxf(sqrtf(t0), 1e-12f);
    }
    __syncthreads();

    int i2 = tid >> 4, j2 = tid & 15;
    float a = 0.f;
    #pragma unroll
    for (int s2 = 0; s2 < 16; ++s2) a += sm[s2 * 256 + i2 * 16 + j2];
    a = a / (qqs[i2] * kks[j2]) * temp[h];

    unsigned mask = 0xFFFFFFFFu;
    float mx = a;
    for (int w = 8; w > 0; w >>= 1) mx = fmaxf(mx, __shfl_xor_sync(mask, mx, w, 16));
    float e = expf(a - mx);
    float ssum = e;
    for (int w = 8; w > 0; w >>= 1) ssum += __shfl_xor_sync(mask, ssum, w, 16);
    attnOut[(((size_t)b * HEADS_ + h) * 16 + i2) * 16 + j2] = e / ssum;
}

// ---------------- M[b] = po @ blockdiag(attn[b]) : [C_, C_] ----------------
__global__ void poattnk(const float* __restrict__ po, const float* __restrict__ attn,
                        float* __restrict__ M)
{
    int b = blockIdx.x;
    __shared__ float at[HEADS_ * 256];
    for (int i = threadIdx.x; i < HEADS_ * 256; i += 256) at[i] = attn[(size_t)b * HEADS_ * 256 + i];
    __syncthreads();
    for (int idx = threadIdx.x; idx < C_ * C_; idx += 256) {
        int o = idx >> 7, cj = idx & 127;
        int h = cj >> 4, j = cj & 15;
        float s = 0.f;
        #pragma unroll
        for (int i = 0; i < 16; ++i) s += po[o * C_ + h * 16 + i] * at[h * 256 + i * 16 + j];
        M[((size_t)b * C_ + o) * C_ + cj] = s;
    }
}

// ---------------- global average pool per (b,c) ----------------
__global__ void capoolk(const float* __restrict__ X, float* __restrict__ pool)
{
    int c = blockIdx.x, b = blockIdx.y;
    const float* xb = X + ((size_t)b * C_ + c) * N_;
    float s = 0.f;
    for (int n = threadIdx.x * 4; n < N_; n += 1024) {
        float4 v = *(const float4*)&xb[n];
        s += v.x + v.y + v.z + v.w;
    }
    __shared__ float red[256];
    red[threadIdx.x] = s; __syncthreads();
    for (int st = 128; st > 0; st >>= 1) {
        if (threadIdx.x < st) red[threadIdx.x] += red[threadIdx.x + st];
        __syncthreads();
    }
    if (threadIdx.x == 0) pool[b * C_ + c] = red[0] * (1.f / N_);
}

// ---------------- CA: relu FC (128->8) + sigmoid FC (8->128) ----------------
__global__ void cafck(const float* __restrict__ pool,
                      const float* __restrict__ w1, const float* __restrict__ b1,
                      const float* __restrict__ w2, const float* __restrict__ b2,
                      float* __restrict__ cas)
{
    int b = blockIdx.x, t = threadIdx.x;
    __shared__ float pl[C_];
    __shared__ float hid[8];
    pl[t] = pool[b * C_ + t];
    __syncthreads();
    if (t < 8) {
        float s = b1[t];
        #pragma unroll 4
        for (int c = 0; c < C_; ++c) s += w1[t * C_ + c] * pl[c];
        hid[t] = fmaxf(s, 0.f);
    }
    __syncthreads();
    float s = b2[t];
    #pragma unroll
    for (int r = 0; r < 8; ++r) s += w2[t * 8 + r] * hid[r];
    cas[b * C_ + t] = 1.f / (1.f + expf(-s));
}

// ---------------- x_out = fuse * ca + origin (float4) ----------------
__global__ void scaleaddk(const float* __restrict__ fuse, const float* __restrict__ cas,
                          const float* __restrict__ origin, float* __restrict__ Y)
{
    size_t idx4 = ((size_t)blockIdx.x * 256 + threadIdx.x) * 4;
    int b = (int)(idx4 / ((size_t)C_ * N_));
    int c = (int)((idx4 / N_) % C_);
    float sc = cas[b * C_ + c];
    float4 f = *(const float4*)&fuse[idx4];
    float4 o = *(const float4*)&origin[idx4];
    *(float4*)&Y[idx4] = make_float4(f.x * sc + o.x, f.y * sc + o.y,
                                     f.z * sc + o.z, f.w * sc + o.w);
}

// ---------------- host ----------------
extern "C" void kernel_launch(void* const* d_in, const int* in_sizes, int n_in,
                              void* d_out, int out_size)
{
    (void)in_sizes; (void)n_in; (void)out_size;
    const float* origin  = (const float*)d_in[0];
    const float* low     = (const float*)d_in[1];
    const float* high    = (const float*)d_in[2];
    const float* norm1_w = (const float*)d_in[3];
    const float* norm1_b = (const float*)d_in[4];
    const float* norm_1_w= (const float*)d_in[5];
    const float* norm_1_b= (const float*)d_in[6];
    const float* norm2_w = (const float*)d_in[7];
    const float* norm2_b = (const float*)d_in[8];
    const float* a1_q    = (const float*)d_in[9];
    const float* a1_qdw  = (const float*)d_in[10];
    const float* a1_kv   = (const float*)d_in[11];
    const float* a1_kvdw = (const float*)d_in[12];
    const float* a1_po   = (const float*)d_in[13];
    const float* a1_temp = (const float*)d_in[14];
    const float* a2_q    = (const float*)d_in[15];
    const float* a2_qdw  = (const float*)d_in[16];
    const float* a2_kv   = (const float*)d_in[17];
    const float* a2_kvdw = (const float*)d_in[18];
    const float* a2_po   = (const float*)d_in[19];
    const float* a2_temp = (const float*)d_in[20];
    const float* conv1_w = (const float*)d_in[21];
    const float* ca1_w   = (const float*)d_in[22];
    const float* ca1_b   = (const float*)d_in[23];
    const float* ca2_w   = (const float*)d_in[24];
    const float* ca2_b   = (const float*)d_in[25];
    const float* ffn_pi  = (const float*)d_in[26];
    const float* ffn_dw  = (const float*)d_in[27];
    const float* ffn_po  = (const float*)d_in[28];
    float* out = (float*)d_out;

    float *bufCa, *bufCb, *bufCc, *buf2Ca, *buf2Cb, *bufHa, *bufHb;
    float *attnw, *Mw, *pool, *cas;
    cudaGetSymbolAddress((void**)&bufCa, g_bufCa);
    cudaGetSymbolAddress((void**)&bufCb, g_bufCb);
    cudaGetSymbolAddress((void**)&bufCc, g_bufCc);
    cudaGetSymbolAddress((void**)&buf2Ca, g_buf2Ca);
    cudaGetSymbolAddress((void**)&buf2Cb, g_buf2Cb);
    cudaGetSymbolAddress((void**)&bufHa, g_bufHa);
    cudaGetSymbolAddress((void**)&bufHb, g_bufHb);
    cudaGetSymbolAddress((void**)&attnw, g_attnw);
    cudaGetSymbolAddress((void**)&Mw, g_Mw);
    cudaGetSymbolAddress((void**)&pool, g_pool);
    cudaGetSymbolAddress((void**)&cas, g_cas);

    dim3 tb(256);
    dim3 gLN(N_ / 256, B_);
    dim3 gG_C(N_ / 128, 1, B_);
    dim3 gG_2C(N_ / 128, 2, B_);
    dim3 gG_H(N_ / 128, (HID2_ + 127) / 128, B_);
    dim3 gRow(C_, B_);
    dim3 gAttn(HEADS_, B_);
    dim3 gDW_C(Hh_ / 8, C_, B_);
    dim3 gDW_2C(Hh_ / 8, C2_, B_);
    dim3 gDW_H(Hh_ / 8, HID_, B_);

    // ===== path 1: x_low = low + attn(kv=LN(low), q=high) =====
    lnk<<<gLN, tb>>>(low, norm1_w, norm1_b, bufCa);
    sgemm128<<<gG_C, tb>>>(a1_q, high, bufCb, nullptr, C_, C_, C_, C_, 0, 0, 0);
    dwconv3k<<<gDW_C, tb>>>(bufCb, a1_qdw, bufCc, C_);
    sgemm128<<<gG_2C, tb>>>(a1_kv, bufCa, buf2Ca, nullptr, C2_, C_, C_, C2_, 0, 0, 0);
    dwconv3k<<<gDW_2C, tb>>>(buf2Ca, a1_kvdw, buf2Cb, C2_);
    attnk<<<gAttn, tb>>>(bufCc, buf2Cb, a1_temp, attnw);
    poattnk<<<dim3(B_), tb>>>(a1_po, attnw, Mw);
    // Y[:,0:C] = M_b @ v + low   (v = KV[C:2C])
    sgemm128<<<gG_C, tb>>>(Mw, buf2Cb + (size_t)C_ * N_, buf2Ca, low,
                           C_, C_, C2_, C2_, 0, 1, C_ * C_);

    // ===== path 2: x_high = high + attn(kv=LN(high), q=low) =====
    lnk<<<gLN, tb>>>(high, norm_1_w, norm_1_b, bufCa);
    sgemm128<<<gG_C, tb>>>(a2_q, low, bufCb, nullptr, C_, C_, C_, C_, 0, 0, 0);
    dwconv3k<<<gDW_C, tb>>>(bufCb, a2_qdw, bufCc, C_);
    sgemm128<<<gG_2C, tb>>>(a2_kv, bufCa, buf2Cb, nullptr, C2_, C_, C_, C2_, 0, 0, 0);
    dwconv3k<<<gDW_2C, tb>>>(buf2Cb, a2_kvdw, bufHa, C2_);  // bufHa as 2C scratch
    attnk<<<gAttn, tb>>>(bufCc, bufHa, a2_temp, attnw);
    poattnk<<<dim3(B_), tb>>>(a2_po, attnw, Mw);
    // Y[:,C:2C] = M_b @ v + high
    sgemm128<<<gG_C, tb>>>(Mw, bufHa + (size_t)C_ * N_, buf2Ca, high,
                           C_, C_, C2_, C2_, C_, 1, C_ * C_);

    // ===== fuse: conv1(concat) -> CA -> + origin =====
    sgemm128<<<gG_C, tb>>>(conv1_w, buf2Ca, bufCa, nullptr, C_, C2_, C2_, C_, 0, 0, 0);
    capoolk<<<gRow, tb>>>(bufCa, pool);
    cafck<<<dim3(B_), dim3(128)>>>(pool, ca1_w, ca1_b, ca2_w, ca2_b, cas);
    scaleaddk<<<dim3((unsigned)(((size_t)B_ * C_ * N_) / 1024)), tb>>>(bufCa, cas, origin, bufCb);

    // ===== FFN with residual =====
    lnk<<<gLN, tb>>>(bufCb, norm2_w, norm2_b, bufCa);
    sgemm128<<<gG_H, tb>>>(ffn_pi, bufCa, bufHa, nullptr, HID2_, C_, C_, HID2_, 0, 0, 0);
    dwgatek<<<gDW_H, tb>>>(bufHa, ffn_dw, bufHb);
    sgemm128<<<gG_C, tb>>>(ffn_po, bufHb, out, bufCb, C_, HID_, HID_, C_, 0, 3, 0);
}

// round 7
// speedup vs baseline: 1.5196x; 1.1137x over previous
#include <cuda_runtime.h>
#include <math.h>

#define B_    8
#define C_    128
#define Hh_   128
#define Ww_   128
#define N_    16384      // H*W
#define HEADS_ 8
#define CH_   16         // C/HEADS
#define HID_  340
#define HID2_ 680
#define C2_   256
#define NCHUNK_ 16
#define CHUNKN_ (N_ / NCHUNK_)   // 1024

// ---------------- static scratch (no allocations allowed) ----------------
__device__ float g_bufCb[(size_t)B_ * C_ * N_];
__device__ float g_bufCc[(size_t)B_ * C_ * N_];
__device__ float g_buf2Ca[(size_t)B_ * C2_ * N_];
__device__ float g_buf2Cb[(size_t)B_ * C2_ * N_];
__device__ float g_bufHa[(size_t)B_ * HID2_ * N_];
__device__ float g_bufHb[(size_t)B_ * HID_ * N_];
__device__ float g_xout[(size_t)B_ * C_ * N_];
__device__ float g_mu[B_ * N_];
__device__ float g_inv[B_ * N_];
__device__ float g_attnp[B_ * HEADS_ * NCHUNK_ * 288];
__device__ float g_attnw[B_ * HEADS_ * CH_ * CH_];
__device__ float g_Mw[B_ * C_ * C_];
__device__ float g_pool[B_ * C_];
__device__ float g_cas[B_ * C_];

// packed f32x2 helpers (Blackwell FFMA2 — PTX-only)
#define FMA2(d, a, b) asm("fma.rn.f32x2 %0, %1, %2, %0;" : "+l"(d) : "l"(a), "l"(b))
#define UNPK2(lo, hi, s) asm("mov.b64 {%0, %1}, %2;" : "=f"(lo), "=f"(hi) : "l"(s))

// ---------------- per-pixel LN stats only: mu, inv ----------------
__global__ void lnstatsk(const float* __restrict__ X, float* __restrict__ mu,
                         float* __restrict__ inv)
{
    int p = blockIdx.x * 256 + threadIdx.x;
    int b = blockIdx.y;
    const float* xb = X + (size_t)b * C_ * N_ + p;
    float s = 0.f, ss = 0.f;
    #pragma unroll 4
    for (int c = 0; c < C_; ++c) {
        float v = xb[(size_t)c * N_];
        s += v; ss += v * v;
    }
    float m = s * (1.f / C_);
    float var = ss * (1.f / C_) - m * m;
    mu[b * N_ + p] = m;
    inv[b * N_ + p] = rsqrtf(var + 1e-5f);
}

// ---------------- fused: x_out = fuse*ca + origin ; write x_out + LN stats ----------------
__global__ void scaleaddstatsk(const float* __restrict__ fuse, const float* __restrict__ cas,
                               const float* __restrict__ origin, float* __restrict__ Y,
                               float* __restrict__ mu, float* __restrict__ inv)
{
    int p = blockIdx.x * 256 + threadIdx.x;
    int b = blockIdx.y;
    __shared__ float sc[C_];
    for (int i = threadIdx.x; i < C_; i += 256) sc[i] = cas[b * C_ + i];
    __syncthreads();
    const size_t base = (size_t)b * C_ * N_ + p;
    float s = 0.f, ss = 0.f;
    #pragma unroll 4
    for (int c = 0; c < C_; ++c) {
        float v = fuse[base + (size_t)c * N_] * sc[c] + origin[base + (size_t)c * N_];
        Y[base + (size_t)c * N_] = v;
        s += v; ss += v * v;
    }
    float m = s * (1.f / C_);
    float var = ss * (1.f / C_) - m * m;
    mu[b * N_ + p] = m;
    inv[b * N_ + p] = rsqrtf(var + 1e-5f);
}

// ---------------- SGEMM 128x128x16, 8x8 micro-tile, f32x2, W pre-duplicated in smem ----------
// Y[b, Yoff+o, p] = sum_c W[o,c] LN?(X[b,c,p])  (+resid, +nan_to_num)
// flags: 1=residual add, 2=nan_to_num, 4=apply LN to X on load
__global__ void __launch_bounds__(256, 2)
sgemm128(const float* __restrict__ Wm, const float* __restrict__ X,
         float* __restrict__ Y, const float* __restrict__ R,
         const float* __restrict__ lnMu, const float* __restrict__ lnInv,
         const float* __restrict__ lnW, const float* __restrict__ lnB,
         int Cout, int Cin, int XCtot, int YCtot, int Yoff,
         int flags, int WstrideB)
{
    const int bz = blockIdx.z;
    const int o0 = blockIdx.y * 128;
    const int p0 = blockIdx.x * 128;
    const float* Wb = Wm + (size_t)bz * WstrideB;
    const float* Xb = X + (size_t)bz * XCtot * N_;
    const int lnOn = flags & 4;

    __shared__ __align__(16) float2 Ws2[2][16][128];   // 32KB, value duplicated
    __shared__ __align__(16) float  Xs[2][16][128];    // 16KB

    const int tid = threadIdx.x;
    const int tx = tid & 15, ty = tid >> 4;

    unsigned long long acc2[8][4];
    #pragma unroll
    for (int i = 0; i < 8; ++i)
        #pragma unroll
        for (int j = 0; j < 4; ++j) acc2[i][j] = 0ULL;

    float wr[2][4];
    float4 xr[2];
    const int ktiles = (Cin + 15) >> 4;

    // ---- preload tile 0 into regs ----
    {
        #pragma unroll
        for (int u = 0; u < 2; ++u) {
            int e4 = tid + 256 * u;
            int row = e4 & 127, kq = e4 >> 7;
            int o = o0 + row;
            #pragma unroll
            for (int t = 0; t < 4; ++t) {
                int kk = kq * 4 + t;
                wr[u][t] = (o < Cout && kk < Cin) ? Wb[(size_t)o * Cin + kk] : 0.f;
            }
        }
        #pragma unroll
        for (int u = 0; u < 2; ++u) {
            int e = tid + 256 * u;
            int row = e >> 5, cq = e & 31;
            float4 v = (row < Cin) ? *(const float4*)&Xb[(size_t)row * N_ + p0 + cq * 4]
                                   : make_float4(0.f, 0.f, 0.f, 0.f);
            if (lnOn && row < Cin) {
                int pix = p0 + cq * 4;
                float4 m  = *(const float4*)&lnMu[(size_t)bz * N_ + pix];
                float4 iv = *(const float4*)&lnInv[(size_t)bz * N_ + pix];
                float wv = lnW[row], bv = lnB[row];
                v.x = (v.x - m.x) * iv.x * wv + bv;
                v.y = (v.y - m.y) * iv.y * wv + bv;
                v.z = (v.z - m.z) * iv.z * wv + bv;
                v.w = (v.w - m.w) * iv.w * wv + bv;
            }
            xr[u] = v;
        }
    }

    int buf = 0;
    for (int kt = 0; kt < ktiles; ++kt) {
        // ---- store regs -> smem[buf] ----
        #pragma unroll
        for (int u = 0; u < 2; ++u) {
            int e4 = tid + 256 * u;
            int row = e4 & 127, kq = e4 >> 7;
            #pragma unroll
            for (int t = 0; t < 4; ++t)
                Ws2[buf][kq * 4 + t][row] = make_float2(wr[u][t], wr[u][t]);
        }
        #pragma unroll
        for (int u = 0; u < 2; ++u) {
            int e = tid + 256 * u;
            int row = e >> 5, cq = e & 31;
            *(float4*)&Xs[buf][row][cq * 4] = xr[u];
        }
        __syncthreads();

        // ---- prefetch next tile (overlaps compute) ----
        if (kt + 1 < ktiles) {
            int k0 = (kt + 1) * 16;
            #pragma unroll
            for (int u = 0; u < 2; ++u) {
                int e4 = tid + 256 * u;
                int row = e4 & 127, kq = e4 >> 7;
                int o = o0 + row;
                #pragma unroll
                for (int t = 0; t < 4; ++t) {
                    int kk = k0 + kq * 4 + t;
                    wr[u][t] = (o < Cout && kk < Cin) ? Wb[(size_t)o * Cin + kk] : 0.f;
                }
            }
            #pragma unroll
            for (int u = 0; u < 2; ++u) {
                int e = tid + 256 * u;
                int row = e >> 5, cq = e & 31;
                int kk = k0 + row;
                float4 v = (kk < Cin) ? *(const float4*)&Xb[(size_t)kk * N_ + p0 + cq * 4]
                                      : make_float4(0.f, 0.f, 0.f, 0.f);
                if (lnOn && kk < Cin) {
                    int pix = p0 + cq * 4;
                    float4 m  = *(const float4*)&lnMu[(size_t)bz * N_ + pix];
                    float4 iv = *(const float4*)&lnInv[(size_t)bz * N_ + pix];
                    float wv = lnW[kk], bv = lnB[kk];
                    v.x = (v.x - m.x) * iv.x * wv + bv;
                    v.y = (v.y - m.y) * iv.y * wv + bv;
                    v.z = (v.z - m.z) * iv.z * wv + bv;
                    v.w = (v.w - m.w) * iv.w * wv + bv;
                }
                xr[u] = v;
            }
        }

        // ---- compute (packed f32x2, vector W loads) ----
        #pragma unroll
        for (int k = 0; k < 16; ++k) {
            ulonglong2 q0 = *(const ulonglong2*)&Xs[buf][k][tx * 8];
            ulonglong2 q1 = *(const ulonglong2*)&Xs[buf][k][tx * 8 + 4];
            unsigned long long bb0 = q0.x, bb1 = q0.y, bb2 = q1.x, bb3 = q1.y;
            const ulonglong2* wrow = (const ulonglong2*)&Ws2[buf][k][ty * 8];
            ulonglong2 w01 = wrow[0], w23 = wrow[1], w45 = wrow[2], w67 = wrow[3];
            unsigned long long av[8] = {w01.x, w01.y, w23.x, w23.y,
                                        w45.x, w45.y, w67.x, w67.y};
            #pragma unroll
            for (int i = 0; i < 8; ++i) {
                FMA2(acc2[i][0], av[i], bb0);
                FMA2(acc2[i][1], av[i], bb1);
                FMA2(acc2[i][2], av[i], bb2);
                FMA2(acc2[i][3], av[i], bb3);
            }
        }
        buf ^= 1;
    }

    // ---- epilogue ----
    const int doResid = flags & 1, doFinal = flags & 2;
    #pragma unroll
    for (int i = 0; i < 8; ++i) {
        int o = o0 + ty * 8 + i;
        if (o >= Cout) continue;
        size_t ybase = ((size_t)bz * YCtot + Yoff + o) * N_ + p0 + tx * 8;
        float v[8];
        #pragma unroll
        for (int j = 0; j < 4; ++j) UNPK2(v[2 * j], v[2 * j + 1], acc2[i][j]);
        if (doResid) {
            size_t rbase = ((size_t)bz * Cout + o) * N_ + p0 + tx * 8;
            float4 r0 = *(const float4*)&R[rbase];
            float4 r1 = *(const float4*)&R[rbase + 4];
            v[0] += r0.x; v[1] += r0.y; v[2] += r0.z; v[3] += r0.w;
            v[4] += r1.x; v[5] += r1.y; v[6] += r1.z; v[7] += r1.w;
        }
        if (doFinal) {
            #pragma unroll
            for (int j = 0; j < 8; ++j) v[j] = isfinite(v[j]) ? v[j] : 1e-5f;
        }
        *(float4*)&Y[ybase]     = make_float4(v[0], v[1], v[2], v[3]);
        *(float4*)&Y[ybase + 4] = make_float4(v[4], v[5], v[6], v[7]);
    }
}

// ---------------- depthwise 3x3, SAME padding (smem-tiled, 8 rows/block) ----------------
__global__ void dwconv3k(const float* __restrict__ X, const float* __restrict__ Wd,
                         float* __restrict__ Y, int CHn)
{
    int c = blockIdx.y, b = blockIdx.z;
    int y0 = blockIdx.x * 8;
    int tid = threadIdx.x;
    const float* xb = X + ((size_t)b * CHn + c) * N_;
    __shared__ float t[10][128];
    for (int i = tid; i < 320; i += 256) {
        int r = i >> 5, xq = i & 31;
        int yy = y0 - 1 + r;
        float4 v = make_float4(0.f, 0.f, 0.f, 0.f);
        if (yy >= 0 && yy < Hh_) v = *(const float4*)&xb[yy * 128 + xq * 4];
        *(float4*)&t[r][xq * 4] = v;
    }
    float w[9];
    #pragma unroll
    for (int q = 0; q < 9; ++q) w[q] = Wd[c * 9 + q];
    __syncthreads();
    int r = tid >> 5;
    int lx = tid & 31;
    float* yo = Y + ((size_t)b * CHn + c) * N_ + (y0 + r) * 128;
    #pragma unroll
    for (int u = 0; u < 4; ++u) {
        int x = u * 32 + lx;
        float s = 0.f;
        #pragma unroll
        for (int dy = 0; dy < 3; ++dy) {
            const float* row = t[r + dy];
            float m  = row[x];
            float l  = (x > 0)   ? row[x - 1] : 0.f;
            float rr = (x < 127) ? row[x + 1] : 0.f;
            s += l * w[dy * 3] + m * w[dy * 3 + 1] + rr * w[dy * 3 + 2];
        }
        yo[x] = s;
    }
}

// ---------------- fused FFN dwconv(680) + gelu-gate -> 340 (smem-tiled) ----------------
__global__ void dwgatek(const float* __restrict__ X, const float* __restrict__ Wd,
                        float* __restrict__ Y)
{
    int c = blockIdx.y, b = blockIdx.z;
    int y0 = blockIdx.x * 8;
    int tid = threadIdx.x;
    const float* x1b = X + ((size_t)b * HID2_ + c) * N_;
    const float* x2b = X + ((size_t)b * HID2_ + c + HID_) * N_;
    __shared__ float t1[10][128];
    __shared__ float t2[10][128];
    for (int i = tid; i < 320; i += 256) {
        int r = i >> 5, xq = i & 31;
        int yy = y0 - 1 + r;
        float4 v1 = make_float4(0.f, 0.f, 0.f, 0.f);
        float4 v2 = v1;
        if (yy >= 0 && yy < Hh_) {
            v1 = *(const float4*)&x1b[yy * 128 + xq * 4];
            v2 = *(const float4*)&x2b[yy * 128 + xq * 4];
        }
        *(float4*)&t1[r][xq * 4] = v1;
        *(float4*)&t2[r][xq * 4] = v2;
    }
    float w1[9], w2[9];
    #pragma unroll
    for (int q = 0; q < 9; ++q) { w1[q] = Wd[c * 9 + q]; w2[q] = Wd[(c + HID_) * 9 + q]; }
    __syncthreads();
    int r = tid >> 5;
    int lx = tid & 31;
    float* yo = Y + ((size_t)b * HID_ + c) * N_ + (y0 + r) * 128;
    #pragma unroll
    for (int u = 0; u < 4; ++u) {
        int x = u * 32 + lx;
        float s1 = 0.f, s2 = 0.f;
        #pragma unroll
        for (int dy = 0; dy < 3; ++dy) {
            const float* r1 = t1[r + dy];
            const float* r2 = t2[r + dy];
            float m1  = r1[x],  m2  = r2[x];
            float l1  = (x > 0)   ? r1[x - 1] : 0.f;
            float l2  = (x > 0)   ? r2[x - 1] : 0.f;
            float rr1 = (x < 127) ? r1[x + 1] : 0.f;
            float rr2 = (x < 127) ? r2[x + 1] : 0.f;
            s1 += l1 * w1[dy * 3] + m1 * w1[dy * 3 + 1] + rr1 * w1[dy * 3 + 2];
            s2 += l2 * w2[dy * 3] + m2 * w2[dy * 3 + 1] + rr2 * w2[dy * 3 + 2];
        }
        float ge = 0.5f * s1 * (1.f + erff(s1 * 0.70710678118654752f));
        yo[x] = ge * s2;
    }
}

// ---------------- attention partials: per N-chunk Gram + norm partials ----------------
__global__ void attnpartk(const float* __restrict__ Q, const float* __restrict__ KV,
                          float* __restrict__ part)
{
    int chunk = blockIdx.x, h = blockIdx.y, b = blockIdx.z;
    const float* qb = Q  + ((size_t)b * C_  + h * CH_) * N_;
    const float* kb = KV + ((size_t)b * C2_ + h * CH_) * N_;

    __shared__ float sm[16 * 16 * 16];
    __shared__ float qqp[256], kkp[256];
    float* qs = sm;
    float* ks = sm + 1024;

    int tid = threadIdx.x;
    int i = tid & 15, s = tid >> 4;
    float acc[16];
    #pragma unroll
    for (int j = 0; j < 16; ++j) acc[j] = 0.f;
    float qq = 0.f, kk = 0.f;

    int nbeg = chunk * CHUNKN_;
    for (int n0 = nbeg; n0 < nbeg + CHUNKN_; n0 += 64) {
        #pragma unroll
        for (int u = 0; u < 4; ++u) {
            int e = tid + 256 * u;
            int r = e >> 6, cc = e & 63;
            qs[r * 64 + cc] = qb[(size_t)r * N_ + n0 + cc];
            ks[r * 64 + cc] = kb[(size_t)r * N_ + n0 + cc];
        }
        __syncthreads();
        #pragma unroll
        for (int t = 0; t < 4; ++t) {
            float qv = qs[i * 64 + s * 4 + t];
            float kv = ks[i * 64 + s * 4 + t];
            qq += qv * qv;
            kk += kv * kv;
            #pragma unroll
            for (int j = 0; j < 16; ++j) acc[j] += qv * ks[j * 64 + s * 4 + t];
        }
        __syncthreads();
    }
    qqp[s * 16 + i] = qq;
    kkp[s * 16 + i] = kk;
    #pragma unroll
    for (int j = 0; j < 16; ++j) sm[s * 256 + i * 16 + j] = acc[j];
    __syncthreads();

    float* pb = part + (((size_t)(b * HEADS_ + h)) * NCHUNK_ + chunk) * 288;
    int i2 = tid >> 4, j2 = tid & 15;
    float a = 0.f;
    #pragma unroll
    for (int s2 = 0; s2 < 16; ++s2) a += sm[s2 * 256 + i2 * 16 + j2];
    pb[i2 * 16 + j2] = a;
    if (tid < 16) {
        float t0 = 0.f;
        #pragma unroll
        for (int s2 = 0; s2 < 16; ++s2) t0 += qqp[s2 * 16 + tid];
        pb[256 + tid] = t0;
    } else if (tid < 32) {
        int j = tid - 16;
        float t0 = 0.f;
        #pragma unroll
        for (int s2 = 0; s2 < 16; ++s2) t0 += kkp[s2 * 16 + j];
        pb[272 + j] = t0;
    }
}

// ---------------- attention finalize: reduce chunks, normalize, softmax ----------------
__global__ void attnfink(const float* __restrict__ part, const float* __restrict__ temp,
                         float* __restrict__ attnOut)
{
    int h = blockIdx.x, b = blockIdx.y;
    const float* pb = part + ((size_t)(b * HEADS_ + h)) * NCHUNK_ * 288;
    __shared__ float qqs[16], kks[16];
    int tid = threadIdx.x;

    float a = 0.f;
    #pragma unroll
    for (int c = 0; c < NCHUNK_; ++c) a += pb[c * 288 + tid];

    if (tid < 16) {
        float t0 = 0.f;
        #pragma unroll
        for (int c = 0; c < NCHUNK_; ++c) t0 += pb[c * 288 + 256 + tid];
        qqs[tid] = fmaxf(sqrtf(t0), 1e-12f);
    } else if (tid < 32) {
        int j = tid - 16;
        float t0 = 0.f;
        #pragma unroll
        for (int c = 0; c < NCHUNK_; ++c) t0 += pb[c * 288 + 272 + j];
        kks[j] = fmaxf(sqrtf(t0), 1e-12f);
    }
    __syncthreads();

    int i2 = tid >> 4, j2 = tid & 15;
    a = a / (qqs[i2] * kks[j2]) * temp[h];

    unsigned mask = 0xFFFFFFFFu;
    float mx = a;
    for (int w = 8; w > 0; w >>= 1) mx = fmaxf(mx, __shfl_xor_sync(mask, mx, w, 16));
    float e = expf(a - mx);
    float ssum = e;
    for (int w = 8; w > 0; w >>= 1) ssum += __shfl_xor_sync(mask, ssum, w, 16);
    attnOut[(((size_t)b * HEADS_ + h) * 16 + i2) * 16 + j2] = e / ssum;
}

// ---------------- M[b] = po @ blockdiag(attn[b]) : [C_, C_] ----------------
__global__ void poattnk(const float* __restrict__ po, const float* __restrict__ attn,
                        float* __restrict__ M)
{
    int b = blockIdx.x;
    __shared__ float at[HEADS_ * 256];
    for (int i = threadIdx.x; i < HEADS_ * 256; i += 256) at[i] = attn[(size_t)b * HEADS_ * 256 + i];
    __syncthreads();
    for (int idx = threadIdx.x; idx < C_ * C_; idx += 256) {
        int o = idx >> 7, cj = idx & 127;
        int h = cj >> 4, j = cj & 15;
        float s = 0.f;
        #pragma unroll
        for (int i = 0; i < 16; ++i) s += po[o * C_ + h * 16 + i] * at[h * 256 + i * 16 + j];
        M[((size_t)b * C_ + o) * C_ + cj] = s;
    }
}

// ---------------- global average pool per (b,c) ----------------
__global__ void capoolk(const float* __restrict__ X, float* __restrict__ pool)
{
    int c = blockIdx.x, b = blockIdx.y;
    const float* xb = X + ((size_t)b * C_ + c) * N_;
    float s = 0.f;
    for (int n = threadIdx.x * 4; n < N_; n += 1024) {
        float4 v = *(const float4*)&xb[n];
        s += v.x + v.y + v.z + v.w;
    }
    __shared__ float red[256];
    red[threadIdx.x] = s; __syncthreads();
    for (int st = 128; st > 0; st >>= 1) {
        if (threadIdx.x < st) red[threadIdx.x] += red[threadIdx.x + st];
        __syncthreads();
    }
    if (threadIdx.x == 0) pool[b * C_ + c] = red[0] * (1.f / N_);
}

// ---------------- CA: relu FC (128->8) + sigmoid FC (8->128) ----------------
__global__ void cafck(const float* __restrict__ pool,
                      const float* __restrict__ w1, const float* __restrict__ b1,
                      const float* __restrict__ w2, const float* __restrict__ b2,
                      float* __restrict__ cas)
{
    int b = blockIdx.x, t = threadIdx.x;
    __shared__ float pl[C_];
    __shared__ float hid[8];
    pl[t] = pool[b * C_ + t];
    __syncthreads();
    if (t < 8) {
        float s = b1[t];
        #pragma unroll 4
        for (int c = 0; c < C_; ++c) s += w1[t * C_ + c] * pl[c];
        hid[t] = fmaxf(s, 0.f);
    }
    __syncthreads();
    float s = b2[t];
    #pragma unroll
    for (int r = 0; r < 8; ++r) s += w2[t * 8 + r] * hid[r];
    cas[b * C_ + t] = 1.f / (1.f + expf(-s));
}

// ---------------- host ----------------
extern "C" void kernel_launch(void* const* d_in, const int* in_sizes, int n_in,
                              void* d_out, int out_size)
{
    (void)in_sizes; (void)n_in; (void)out_size;
    const float* origin  = (const float*)d_in[0];
    const float* low     = (const float*)d_in[1];
    const float* high    = (const float*)d_in[2];
    const float* norm1_w = (const float*)d_in[3];
    const float* norm1_b = (const float*)d_in[4];
    const float* norm_1_w= (const float*)d_in[5];
    const float* norm_1_b= (const float*)d_in[6];
    const float* norm2_w = (const float*)d_in[7];
    const float* norm2_b = (const float*)d_in[8];
    const float* a1_q    = (const float*)d_in[9];
    const float* a1_qdw  = (const float*)d_in[10];
    const float* a1_kv   = (const float*)d_in[11];
    const float* a1_kvdw = (const float*)d_in[12];
    const float* a1_po   = (const float*)d_in[13];
    const float* a1_temp = (const float*)d_in[14];
    const float* a2_q    = (const float*)d_in[15];
    const float* a2_qdw  = (const float*)d_in[16];
    const float* a2_kv   = (const float*)d_in[17];
    const float* a2_kvdw = (const float*)d_in[18];
    const float* a2_po   = (const float*)d_in[19];
    const float* a2_temp = (const float*)d_in[20];
    const float* conv1_w = (const float*)d_in[21];
    const float* ca1_w   = (const float*)d_in[22];
    const float* ca1_b   = (const float*)d_in[23];
    const float* ca2_w   = (const float*)d_in[24];
    const float* ca2_b   = (const float*)d_in[25];
    const float* ffn_pi  = (const float*)d_in[26];
    const float* ffn_dw  = (const float*)d_in[27];
    const float* ffn_po  = (const float*)d_in[28];
    float* out = (float*)d_out;

    float *bufCb, *bufCc, *buf2Ca, *buf2Cb, *bufHa, *bufHb, *xout;
    float *mu, *inv, *attnp, *attnw, *Mw, *pool, *cas;
    cudaGetSymbolAddress((void**)&bufCb, g_bufCb);
    cudaGetSymbolAddress((void**)&bufCc, g_bufCc);
    cudaGetSymbolAddress((void**)&buf2Ca, g_buf2Ca);
    cudaGetSymbolAddress((void**)&buf2Cb, g_buf2Cb);
    cudaGetSymbolAddress((void**)&bufHa, g_bufHa);
    cudaGetSymbolAddress((void**)&bufHb, g_bufHb);
    cudaGetSymbolAddress((void**)&xout, g_xout);
    cudaGetSymbolAddress((void**)&mu, g_mu);
    cudaGetSymbolAddress((void**)&inv, g_inv);
    cudaGetSymbolAddress((void**)&attnp, g_attnp);
    cudaGetSymbolAddress((void**)&attnw, g_attnw);
    cudaGetSymbolAddress((void**)&Mw, g_Mw);
    cudaGetSymbolAddress((void**)&pool, g_pool);
    cudaGetSymbolAddress((void**)&cas, g_cas);

    dim3 tb(256);
    dim3 gLN(N_ / 256, B_);
    dim3 gG_C(N_ / 128, 1, B_);
    dim3 gG_2C(N_ / 128, 2, B_);
    dim3 gG_H(N_ / 128, (HID2_ + 127) / 128, B_);
    dim3 gRow(C_, B_);
    dim3 gAttnP(NCHUNK_, HEADS_, B_);
    dim3 gAttnF(HEADS_, B_);
    dim3 gDW_C(Hh_ / 8, C_, B_);
    dim3 gDW_2C(Hh_ / 8, C2_, B_);
    dim3 gDW_H(Hh_ / 8, HID_, B_);

    // ===== path 1: x_low = low + attn(kv=LN(low), q=high) =====
    lnstatsk<<<gLN, tb>>>(low, mu, inv);
    sgemm128<<<gG_C, tb>>>(a1_q, high, bufCb, nullptr, nullptr, nullptr, nullptr, nullptr,
                           C_, C_, C_, C_, 0, 0, 0);
    dwconv3k<<<gDW_C, tb>>>(bufCb, a1_qdw, bufCc, C_);
    sgemm128<<<gG_2C, tb>>>(a1_kv, low, buf2Ca, nullptr, mu, inv, norm1_w, norm1_b,
                            C2_, C_, C_, C2_, 0, 4, 0);
    dwconv3k<<<gDW_2C, tb>>>(buf2Ca, a1_kvdw, buf2Cb, C2_);
    attnpartk<<<gAttnP, tb>>>(bufCc, buf2Cb, attnp);
    attnfink<<<gAttnF, tb>>>(attnp, a1_temp, attnw);
    poattnk<<<dim3(B_), tb>>>(a1_po, attnw, Mw);
    // Y[:,0:C] = M_b @ v + low   (v = KV[C:2C])
    sgemm128<<<gG_C, tb>>>(Mw, buf2Cb + (size_t)C_ * N_, buf2Ca, low,
                           nullptr, nullptr, nullptr, nullptr,
                           C_, C_, C2_, C2_, 0, 1, C_ * C_);

    // ===== path 2: x_high = high + attn(kv=LN(high), q=low) =====
    lnstatsk<<<gLN, tb>>>(high, mu, inv);
    sgemm128<<<gG_C, tb>>>(a2_q, low, bufCb, nullptr, nullptr, nullptr, nullptr, nullptr,
                           C_, C_, C_, C_, 0, 0, 0);
    dwconv3k<<<gDW_C, tb>>>(bufCb, a2_qdw, bufCc, C_);
    sgemm128<<<gG_2C, tb>>>(a2_kv, high, buf2Cb, nullptr, mu, inv, norm_1_w, norm_1_b,
                            C2_, C_, C_, C2_, 0, 4, 0);
    dwconv3k<<<gDW_2C, tb>>>(buf2Cb, a2_kvdw, bufHa, C2_);  // bufHa as 2C scratch
    attnpartk<<<gAttnP, tb>>>(bufCc, bufHa, attnp);
    attnfink<<<gAttnF, tb>>>(attnp, a2_temp, attnw);
    poattnk<<<dim3(B_), tb>>>(a2_po, attnw, Mw);
    // Y[:,C:2C] = M_b @ v + high
    sgemm128<<<gG_C, tb>>>(Mw, bufHa + (size_t)C_ * N_, buf2Ca, high,
                           nullptr, nullptr, nullptr, nullptr,
                           C_, C_, C2_, C2_, C_, 1, C_ * C_);

    // ===== fuse: conv1(concat) -> CA -> + origin, fused with norm2 stats =====
    sgemm128<<<gG_C, tb>>>(conv1_w, buf2Ca, bufCb, nullptr, nullptr, nullptr, nullptr, nullptr,
                           C_, C2_, C2_, C_, 0, 0, 0);
    capoolk<<<gRow, tb>>>(bufCb, pool);
    cafck<<<dim3(B_), dim3(128)>>>(pool, ca1_w, ca1_b, ca2_w, ca2_b, cas);
    scaleaddstatsk<<<gLN, tb>>>(bufCb, cas, origin, xout, mu, inv);

    // ===== FFN with residual =====
    sgemm128<<<gG_H, tb>>>(ffn_pi, xout, bufHa, nullptr, mu, inv, norm2_w, norm2_b,
                           HID2_, C_, C_, HID2_, 0, 4, 0);
    dwgatek<<<gDW_H, tb>>>(bufHa, ffn_dw, bufHb);
    sgemm128<<<gG_C, tb>>>(ffn_po, bufHb, out, xout, nullptr, nullptr, nullptr, nullptr,
                           C_, HID_, HID_, C_, 0, 3, 0);
}

// round 8
// speedup vs baseline: 1.6845x; 1.1085x over previous
#include <cuda_runtime.h>
#include <math.h>

#define B_    8
#define C_    128
#define Hh_   128
#define Ww_   128
#define N_    16384      // H*W
#define HEADS_ 8
#define CH_   16         // C/HEADS
#define HID_  340
#define HID2_ 680
#define C2_   256
#define NCHUNK_ 16
#define CHUNKN_ (N_ / NCHUNK_)   // 1024

// ---------------- static scratch (no allocations allowed) ----------------
__device__ float g_bufCb[(size_t)B_ * C_ * N_];   // qpre path1 / conv1 out
__device__ float g_bufCc[(size_t)B_ * C_ * N_];   // qpre path2
__device__ float g_bufCd[(size_t)B_ * C_ * N_];   // qdw path1
__device__ float g_bufCe[(size_t)B_ * C_ * N_];   // qdw path2
__device__ float g_buf2Ca[(size_t)B_ * C2_ * N_]; // kvpre path1 / concat out
__device__ float g_buf2Cb[(size_t)B_ * C2_ * N_]; // kvpre path2
__device__ float g_buf2Cc[(size_t)B_ * C2_ * N_]; // kvdw path1
__device__ float g_bufHa[(size_t)B_ * HID2_ * N_];// kvdw path2 (front 2C) / ffn hidden
__device__ float g_bufHb[(size_t)B_ * HID_ * N_]; // gated
__device__ float g_xout[(size_t)B_ * C_ * N_];
__device__ float g_mu[2 * B_ * N_];
__device__ float g_inv[2 * B_ * N_];
__device__ float g_attnp[2 * B_ * HEADS_ * NCHUNK_ * 288];
__device__ float g_attnw[2 * B_ * HEADS_ * CH_ * CH_];
__device__ float g_Mw[2 * B_ * C_ * C_];
__device__ float g_pool[B_ * C_];
__device__ float g_cas[B_ * C_];

// packed f32x2 helpers (Blackwell FFMA2 — PTX-only)
#define FMA2(d, a, b) asm("fma.rn.f32x2 %0, %1, %2, %0;" : "+l"(d) : "l"(a), "l"(b))
#define UNPK2(lo, hi, s) asm("mov.b64 {%0, %1}, %2;" : "=f"(lo), "=f"(hi) : "l"(s))

// ---------------- per-pixel LN stats, both paths in one launch ----------------
__global__ void lnstats2k(const float* __restrict__ X1, const float* __restrict__ X2,
                          float* __restrict__ mu, float* __restrict__ inv)
{
    int p = blockIdx.x * 256 + threadIdx.x;
    int zc = blockIdx.y;                 // 0..2B-1
    int pth = zc >= B_;
    int b = pth ? zc - B_ : zc;
    const float* xb = (pth ? X2 : X1) + (size_t)b * C_ * N_ + p;
    float s = 0.f, ss = 0.f;
    #pragma unroll 4
    for (int c = 0; c < C_; ++c) {
        float v = xb[(size_t)c * N_];
        s += v; ss += v * v;
    }
    float m = s * (1.f / C_);
    float var = ss * (1.f / C_) - m * m;
    mu[(size_t)zc * N_ + p] = m;
    inv[(size_t)zc * N_ + p] = rsqrtf(var + 1e-5f);
}

// ---------------- fused: x_out = fuse*ca + origin ; write x_out + LN stats ----------------
__global__ void scaleaddstatsk(const float* __restrict__ fuse, const float* __restrict__ cas,
                               const float* __restrict__ origin, float* __restrict__ Y,
                               float* __restrict__ mu, float* __restrict__ inv)
{
    int p = blockIdx.x * 256 + threadIdx.x;
    int b = blockIdx.y;
    __shared__ float sc[C_];
    for (int i = threadIdx.x; i < C_; i += 256) sc[i] = cas[b * C_ + i];
    __syncthreads();
    const size_t base = (size_t)b * C_ * N_ + p;
    float s = 0.f, ss = 0.f;
    #pragma unroll 4
    for (int c = 0; c < C_; ++c) {
        float v = fuse[base + (size_t)c * N_] * sc[c] + origin[base + (size_t)c * N_];
        Y[base + (size_t)c * N_] = v;
        s += v; ss += v * v;
    }
    float m = s * (1.f / C_);
    float var = ss * (1.f / C_) - m * m;
    mu[b * N_ + p] = m;
    inv[b * N_ + p] = rsqrtf(var + 1e-5f);
}

// ---------------- SGEMM 128x128x16, dual-path, conflict-free X mapping ----------------
// flags: 1=residual add, 2=nan_to_num, 4=apply LN to X on load
__global__ void __launch_bounds__(256, 2)
sgemm128(const float* __restrict__ W1, const float* __restrict__ X1,
         float* __restrict__ Y1, const float* __restrict__ R1,
         const float* __restrict__ W2, const float* __restrict__ X2,
         float* __restrict__ Y2, const float* __restrict__ R2,
         const float* __restrict__ lnMu, const float* __restrict__ lnInv,
         const float* __restrict__ lnW1, const float* __restrict__ lnB1,
         const float* __restrict__ lnW2, const float* __restrict__ lnB2,
         int Cout, int Cin, int XCtot, int YCtot, int Yoff1, int Yoff2,
         int flags, int WstrideB)
{
    const int bz = blockIdx.z;
    const int pth = bz >= B_;
    const int b = pth ? bz - B_ : bz;
    const int o0 = blockIdx.y * 128;
    const int p0 = blockIdx.x * 128;
    const float* Wb = (pth ? W2 : W1) + (size_t)b * WstrideB;
    const float* Xb = (pth ? X2 : X1) + (size_t)b * XCtot * N_;
    float* Y = pth ? Y2 : Y1;
    const float* R = pth ? R2 : R1;
    const float* lnW = pth ? lnW2 : lnW1;
    const float* lnB = pth ? lnB2 : lnB1;
    const int Yoff = pth ? Yoff2 : Yoff1;
    const int lnOn = flags & 4;

    __shared__ __align__(16) float2 Ws2[2][16][128];
    __shared__ __align__(16) float  Xs[2][16][128];

    const int tid = threadIdx.x;
    const int tx = tid & 15, ty = tid >> 4;

    unsigned long long acc2[8][4];
    #pragma unroll
    for (int i = 0; i < 8; ++i)
        #pragma unroll
        for (int j = 0; j < 4; ++j) acc2[i][j] = 0ULL;

    float wr[2][4];
    float4 xr[2];
    const int ktiles = (Cin + 15) >> 4;

    // ---- preload tile 0 ----
    {
        #pragma unroll
        for (int u = 0; u < 2; ++u) {
            int e4 = tid + 256 * u;
            int row = e4 & 127, kq = e4 >> 7;
            int o = o0 + row;
            #pragma unroll
            for (int t = 0; t < 4; ++t) {
                int kk = kq * 4 + t;
                wr[u][t] = (o < Cout && kk < Cin) ? Wb[(size_t)o * Cin + kk] : 0.f;
            }
        }
        #pragma unroll
        for (int u = 0; u < 2; ++u) {
            int e = tid + 256 * u;
            int row = e >> 5, cq = e & 31;
            float4 v = (row < Cin) ? *(const float4*)&Xb[(size_t)row * N_ + p0 + cq * 4]
                                   : make_float4(0.f, 0.f, 0.f, 0.f);
            if (lnOn && row < Cin) {
                int pix = p0 + cq * 4;
                float4 m  = *(const float4*)&lnMu[(size_t)bz * N_ + pix];
                float4 iv = *(const float4*)&lnInv[(size_t)bz * N_ + pix];
                float wv = lnW[row], bv = lnB[row];
                v.x = (v.x - m.x) * iv.x * wv + bv;
                v.y = (v.y - m.y) * iv.y * wv + bv;
                v.z = (v.z - m.z) * iv.z * wv + bv;
                v.w = (v.w - m.w) * iv.w * wv + bv;
            }
            xr[u] = v;
        }
    }

    int buf = 0;
    for (int kt = 0; kt < ktiles; ++kt) {
        #pragma unroll
        for (int u = 0; u < 2; ++u) {
            int e4 = tid + 256 * u;
            int row = e4 & 127, kq = e4 >> 7;
            #pragma unroll
            for (int t = 0; t < 4; ++t)
                Ws2[buf][kq * 4 + t][row] = make_float2(wr[u][t], wr[u][t]);
        }
        #pragma unroll
        for (int u = 0; u < 2; ++u) {
            int e = tid + 256 * u;
            int row = e >> 5, cq = e & 31;
            *(float4*)&Xs[buf][row][cq * 4] = xr[u];
        }
        __syncthreads();

        if (kt + 1 < ktiles) {
            int k0 = (kt + 1) * 16;
            #pragma unroll
            for (int u = 0; u < 2; ++u) {
                int e4 = tid + 256 * u;
                int row = e4 & 127, kq = e4 >> 7;
                int o = o0 + row;
                #pragma unroll
                for (int t = 0; t < 4; ++t) {
                    int kk = k0 + kq * 4 + t;
                    wr[u][t] = (o < Cout && kk < Cin) ? Wb[(size_t)o * Cin + kk] : 0.f;
                }
            }
            #pragma unroll
            for (int u = 0; u < 2; ++u) {
                int e = tid + 256 * u;
                int row = e >> 5, cq = e & 31;
                int kk = k0 + row;
                float4 v = (kk < Cin) ? *(const float4*)&Xb[(size_t)kk * N_ + p0 + cq * 4]
                                      : make_float4(0.f, 0.f, 0.f, 0.f);
                if (lnOn && kk < Cin) {
                    int pix = p0 + cq * 4;
                    float4 m  = *(const float4*)&lnMu[(size_t)bz * N_ + pix];
                    float4 iv = *(const float4*)&lnInv[(size_t)bz * N_ + pix];
                    float wv = lnW[kk], bv = lnB[kk];
                    v.x = (v.x - m.x) * iv.x * wv + bv;
                    v.y = (v.y - m.y) * iv.y * wv + bv;
                    v.z = (v.z - m.z) * iv.z * wv + bv;
                    v.w = (v.w - m.w) * iv.w * wv + bv;
                }
                xr[u] = v;
            }
        }

        // ---- compute: X columns {tx*4..+3} and {64+tx*4..+3} -> conflict-free LDS.128
        #pragma unroll
        for (int k = 0; k < 16; ++k) {
            ulonglong2 q0 = *(const ulonglong2*)&Xs[buf][k][tx * 4];
            ulonglong2 q1 = *(const ulonglong2*)&Xs[buf][k][64 + tx * 4];
            unsigned long long bb0 = q0.x, bb1 = q0.y, bb2 = q1.x, bb3 = q1.y;
            const ulonglong2* wrow = (const ulonglong2*)&Ws2[buf][k][ty * 8];
            ulonglong2 w01 = wrow[0], w23 = wrow[1], w45 = wrow[2], w67 = wrow[3];
            unsigned long long av[8] = {w01.x, w01.y, w23.x, w23.y,
                                        w45.x, w45.y, w67.x, w67.y};
            #pragma unroll
            for (int i = 0; i < 8; ++i) {
                FMA2(acc2[i][0], av[i], bb0);
                FMA2(acc2[i][1], av[i], bb1);
                FMA2(acc2[i][2], av[i], bb2);
                FMA2(acc2[i][3], av[i], bb3);
            }
        }
        buf ^= 1;
    }

    // ---- epilogue ----
    const int doResid = flags & 1, doFinal = flags & 2;
    #pragma unroll
    for (int i = 0; i < 8; ++i) {
        int o = o0 + ty * 8 + i;
        if (o >= Cout) continue;
        size_t ybase0 = ((size_t)b * YCtot + Yoff + o) * N_ + p0 + tx * 4;
        size_t ybase1 = ybase0 + 64;
        float v[8];
        #pragma unroll
        for (int j = 0; j < 4; ++j) UNPK2(v[2 * j], v[2 * j + 1], acc2[i][j]);
        if (doResid) {
            size_t rbase = ((size_t)b * Cout + o) * N_ + p0 + tx * 4;
            float4 r0 = *(const float4*)&R[rbase];
            float4 r1 = *(const float4*)&R[rbase + 64];
            v[0] += r0.x; v[1] += r0.y; v[2] += r0.z; v[3] += r0.w;
            v[4] += r1.x; v[5] += r1.y; v[6] += r1.z; v[7] += r1.w;
        }
        if (doFinal) {
            #pragma unroll
            for (int j = 0; j < 8; ++j) v[j] = isfinite(v[j]) ? v[j] : 1e-5f;
        }
        *(float4*)&Y[ybase0] = make_float4(v[0], v[1], v[2], v[3]);
        *(float4*)&Y[ybase1] = make_float4(v[4], v[5], v[6], v[7]);
    }
}

// ---------------- ALL depthwise 3x3 for both paths (q: C ch, kv: 2C ch) ----------------
__global__ void dwallk(const float* __restrict__ qX1, const float* __restrict__ qX2,
                       const float* __restrict__ qW1, const float* __restrict__ qW2,
                       float* __restrict__ qY1, float* __restrict__ qY2,
                       const float* __restrict__ kX1, const float* __restrict__ kX2,
                       const float* __restrict__ kW1, const float* __restrict__ kW2,
                       float* __restrict__ kY1, float* __restrict__ kY2)
{
    int cidx = blockIdx.y;
    int zc = blockIdx.z;
    int pth = zc >= B_;
    int b = pth ? zc - B_ : zc;
    const float* xb; const float* Wd; float* yb; int c;
    if (cidx < C_) {
        c = cidx;
        xb = (pth ? qX2 : qX1) + ((size_t)b * C_ + c) * N_;
        Wd = (pth ? qW2 : qW1);
        yb = (pth ? qY2 : qY1) + ((size_t)b * C_ + c) * N_;
    } else {
        c = cidx - C_;
        xb = (pth ? kX2 : kX1) + ((size_t)b * C2_ + c) * N_;
        Wd = (pth ? kW2 : kW1);
        yb = (pth ? kY2 : kY1) + ((size_t)b * C2_ + c) * N_;
    }
    int y0 = blockIdx.x * 8;
    int tid = threadIdx.x;
    __shared__ float t[10][128];
    for (int i = tid; i < 320; i += 256) {
        int r = i >> 5, xq = i & 31;
        int yy = y0 - 1 + r;
        float4 v = make_float4(0.f, 0.f, 0.f, 0.f);
        if (yy >= 0 && yy < Hh_) v = *(const float4*)&xb[yy * 128 + xq * 4];
        *(float4*)&t[r][xq * 4] = v;
    }
    float w[9];
    #pragma unroll
    for (int q = 0; q < 9; ++q) w[q] = Wd[c * 9 + q];
    __syncthreads();
    int r = tid >> 5;
    int lx = tid & 31;
    float* yo = yb + (y0 + r) * 128;
    #pragma unroll
    for (int u = 0; u < 4; ++u) {
        int x = u * 32 + lx;
        float s = 0.f;
        #pragma unroll
        for (int dy = 0; dy < 3; ++dy) {
            const float* row = t[r + dy];
            float m  = row[x];
            float l  = (x > 0)   ? row[x - 1] : 0.f;
            float rr = (x < 127) ? row[x + 1] : 0.f;
            s += l * w[dy * 3] + m * w[dy * 3 + 1] + rr * w[dy * 3 + 2];
        }
        yo[x] = s;
    }
}

// ---------------- fused FFN dwconv(680) + gelu-gate -> 340 (smem-tiled) ----------------
__global__ void dwgatek(const float* __restrict__ X, const float* __restrict__ Wd,
                        float* __restrict__ Y)
{
    int c = blockIdx.y, b = blockIdx.z;
    int y0 = blockIdx.x * 8;
    int tid = threadIdx.x;
    const float* x1b = X + ((size_t)b * HID2_ + c) * N_;
    const float* x2b = X + ((size_t)b * HID2_ + c + HID_) * N_;
    __shared__ float t1[10][128];
    __shared__ float t2[10][128];
    for (int i = tid; i < 320; i += 256) {
        int r = i >> 5, xq = i & 31;
        int yy = y0 - 1 + r;
        float4 v1 = make_float4(0.f, 0.f, 0.f, 0.f);
        float4 v2 = v1;
        if (yy >= 0 && yy < Hh_) {
            v1 = *(const float4*)&x1b[yy * 128 + xq * 4];
            v2 = *(const float4*)&x2b[yy * 128 + xq * 4];
        }
        *(float4*)&t1[r][xq * 4] = v1;
        *(float4*)&t2[r][xq * 4] = v2;
    }
    float w1[9], w2[9];
    #pragma unroll
    for (int q = 0; q < 9; ++q) { w1[q] = Wd[c * 9 + q]; w2[q] = Wd[(c + HID_) * 9 + q]; }
    __syncthreads();
    int r = tid >> 5;
    int lx = tid & 31;
    float* yo = Y + ((size_t)b * HID_ + c) * N_ + (y0 + r) * 128;
    #pragma unroll
    for (int u = 0; u < 4; ++u) {
        int x = u * 32 + lx;
        float s1 = 0.f, s2 = 0.f;
        #pragma unroll
        for (int dy = 0; dy < 3; ++dy) {
            const float* r1 = t1[r + dy];
            const float* r2 = t2[r + dy];
            float m1  = r1[x],  m2  = r2[x];
            float l1  = (x > 0)   ? r1[x - 1] : 0.f;
            float l2  = (x > 0)   ? r2[x - 1] : 0.f;
            float rr1 = (x < 127) ? r1[x + 1] : 0.f;
            float rr2 = (x < 127) ? r2[x + 1] : 0.f;
            s1 += l1 * w1[dy * 3] + m1 * w1[dy * 3 + 1] + rr1 * w1[dy * 3 + 2];
            s2 += l2 * w2[dy * 3] + m2 * w2[dy * 3 + 1] + rr2 * w2[dy * 3 + 2];
        }
        float ge = 0.5f * s1 * (1.f + erff(s1 * 0.70710678118654752f));
        yo[x] = ge * s2;
    }
}

// ---------------- attention partials, both paths ----------------
__global__ void attnpartk(const float* __restrict__ Q1, const float* __restrict__ Q2,
                          const float* __restrict__ KV1, const float* __restrict__ KV2,
                          float* __restrict__ part)
{
    int chunk = blockIdx.x, h = blockIdx.y;
    int zc = blockIdx.z;
    int pth = zc >= B_;
    int b = pth ? zc - B_ : zc;
    const float* qb = (pth ? Q2 : Q1)  + ((size_t)b * C_  + h * CH_) * N_;
    const float* kb = (pth ? KV2 : KV1) + ((size_t)b * C2_ + h * CH_) * N_;

    __shared__ float sm[16 * 16 * 16];
    __shared__ float qqp[256], kkp[256];
    float* qs = sm;
    float* ks = sm + 1024;

    int tid = threadIdx.x;
    int i = tid & 15, s = tid >> 4;
    float acc[16];
    #pragma unroll
    for (int j = 0; j < 16; ++j) acc[j] = 0.f;
    float qq = 0.f, kk = 0.f;

    int nbeg = chunk * CHUNKN_;
    for (int n0 = nbeg; n0 < nbeg + CHUNKN_; n0 += 64) {
        #pragma unroll
        for (int u = 0; u < 4; ++u) {
            int e = tid + 256 * u;
            int r = e >> 6, cc = e & 63;
            qs[r * 64 + cc] = qb[(size_t)r * N_ + n0 + cc];
            ks[r * 64 + cc] = kb[(size_t)r * N_ + n0 + cc];
        }
        __syncthreads();
        #pragma unroll
        for (int t = 0; t < 4; ++t) {
            float qv = qs[i * 64 + s * 4 + t];
            float kv = ks[i * 64 + s * 4 + t];
            qq += qv * qv;
            kk += kv * kv;
            #pragma unroll
            for (int j = 0; j < 16; ++j) acc[j] += qv * ks[j * 64 + s * 4 + t];
        }
        __syncthreads();
    }
    qqp[s * 16 + i] = qq;
    kkp[s * 16 + i] = kk;
    #pragma unroll
    for (int j = 0; j < 16; ++j) sm[s * 256 + i * 16 + j] = acc[j];
    __syncthreads();

    float* pb = part + (((size_t)zc * HEADS_ + h) * NCHUNK_ + chunk) * 288;
    int i2 = tid >> 4, j2 = tid & 15;
    float a = 0.f;
    #pragma unroll
    for (int s2 = 0; s2 < 16; ++s2) a += sm[s2 * 256 + i2 * 16 + j2];
    pb[i2 * 16 + j2] = a;
    if (tid < 16) {
        float t0 = 0.f;
        #pragma unroll
        for (int s2 = 0; s2 < 16; ++s2) t0 += qqp[s2 * 16 + tid];
        pb[256 + tid] = t0;
    } else if (tid < 32) {
        int j = tid - 16;
        float t0 = 0.f;
        #pragma unroll
        for (int s2 = 0; s2 < 16; ++s2) t0 += kkp[s2 * 16 + j];
        pb[272 + j] = t0;
    }
}

// ---------------- attention finalize, both paths ----------------
__global__ void attnfink(const float* __restrict__ part, const float* __restrict__ temp1,
                         const float* __restrict__ temp2, float* __restrict__ attnOut)
{
    int h = blockIdx.x;
    int zc = blockIdx.y;
    int pth = zc >= B_;
    const float* temp = pth ? temp2 : temp1;
    const float* pb = part + ((size_t)zc * HEADS_ + h) * NCHUNK_ * 288;
    __shared__ float qqs[16], kks[16];
    int tid = threadIdx.x;

    float a = 0.f;
    #pragma unroll
    for (int c = 0; c < NCHUNK_; ++c) a += pb[c * 288 + tid];

    if (tid < 16) {
        float t0 = 0.f;
        #pragma unroll
        for (int c = 0; c < NCHUNK_; ++c) t0 += pb[c * 288 + 256 + tid];
        qqs[tid] = fmaxf(sqrtf(t0), 1e-12f);
    } else if (tid < 32) {
        int j = tid - 16;
        float t0 = 0.f;
        #pragma unroll
        for (int c = 0; c < NCHUNK_; ++c) t0 += pb[c * 288 + 272 + j];
        kks[j] = fmaxf(sqrtf(t0), 1e-12f);
    }
    __syncthreads();

    int i2 = tid >> 4, j2 = tid & 15;
    a = a / (qqs[i2] * kks[j2]) * temp[h];

    unsigned mask = 0xFFFFFFFFu;
    float mx = a;
    for (int w = 8; w > 0; w >>= 1) mx = fmaxf(mx, __shfl_xor_sync(mask, mx, w, 16));
    float e = expf(a - mx);
    float ssum = e;
    for (int w = 8; w > 0; w >>= 1) ssum += __shfl_xor_sync(mask, ssum, w, 16);
    attnOut[((size_t)zc * HEADS_ + h) * 256 + i2 * 16 + j2] = e / ssum;
}

// ---------------- M[zc] = po @ blockdiag(attn[zc]) : [C_, C_], both paths ----------------
__global__ void poattnk(const float* __restrict__ po1, const float* __restrict__ po2,
                        const float* __restrict__ attn, float* __restrict__ M)
{
    int zc = blockIdx.x;
    const float* po = (zc >= B_) ? po2 : po1;
    __shared__ float at[HEADS_ * 256];
    for (int i = threadIdx.x; i < HEADS_ * 256; i += 256)
        at[i] = attn[(size_t)zc * HEADS_ * 256 + i];
    __syncthreads();
    for (int idx = threadIdx.x; idx < C_ * C_; idx += 256) {
        int o = idx >> 7, cj = idx & 127;
        int h = cj >> 4, j = cj & 15;
        float s = 0.f;
        #pragma unroll
        for (int i = 0; i < 16; ++i) s += po[o * C_ + h * 16 + i] * at[h * 256 + i * 16 + j];
        M[((size_t)zc * C_ + o) * C_ + cj] = s;
    }
}

// ---------------- global average pool per (b,c) ----------------
__global__ void capoolk(const float* __restrict__ X, float* __restrict__ pool)
{
    int c = blockIdx.x, b = blockIdx.y;
    const float* xb = X + ((size_t)b * C_ + c) * N_;
    float s = 0.f;
    for (int n = threadIdx.x * 4; n < N_; n += 1024) {
        float4 v = *(const float4*)&xb[n];
        s += v.x + v.y + v.z + v.w;
    }
    __shared__ float red[256];
    red[threadIdx.x] = s; __syncthreads();
    for (int st = 128; st > 0; st >>= 1) {
        if (threadIdx.x < st) red[threadIdx.x] += red[threadIdx.x + st];
        __syncthreads();
    }
    if (threadIdx.x == 0) pool[b * C_ + c] = red[0] * (1.f / N_);
}

// ---------------- CA: relu FC (128->8) + sigmoid FC (8->128) ----------------
__global__ void cafck(const float* __restrict__ pool,
                      const float* __restrict__ w1, const float* __restrict__ b1,
                      const float* __restrict__ w2, const float* __restrict__ b2,
                      float* __restrict__ cas)
{
    int b = blockIdx.x, t = threadIdx.x;
    __shared__ float pl[C_];
    __shared__ float hid[8];
    pl[t] = pool[b * C_ + t];
    __syncthreads();
    if (t < 8) {
        float s = b1[t];
        #pragma unroll 4
        for (int c = 0; c < C_; ++c) s += w1[t * C_ + c] * pl[c];
        hid[t] = fmaxf(s, 0.f);
    }
    __syncthreads();
    float s = b2[t];
    #pragma unroll
    for (int r = 0; r < 8; ++r) s += w2[t * 8 + r] * hid[r];
    cas[b * C_ + t] = 1.f / (1.f + expf(-s));
}

// ---------------- host ----------------
extern "C" void kernel_launch(void* const* d_in, const int* in_sizes, int n_in,
                              void* d_out, int out_size)
{
    (void)in_sizes; (void)n_in; (void)out_size;
    const float* origin  = (const float*)d_in[0];
    const float* low     = (const float*)d_in[1];
    const float* high    = (const float*)d_in[2];
    const float* norm1_w = (const float*)d_in[3];
    const float* norm1_b = (const float*)d_in[4];
    const float* norm_1_w= (const float*)d_in[5];
    const float* norm_1_b= (const float*)d_in[6];
    const float* norm2_w = (const float*)d_in[7];
    const float* norm2_b = (const float*)d_in[8];
    const float* a1_q    = (const float*)d_in[9];
    const float* a1_qdw  = (const float*)d_in[10];
    const float* a1_kv   = (const float*)d_in[11];
    const float* a1_kvdw = (const float*)d_in[12];
    const float* a1_po   = (const float*)d_in[13];
    const float* a1_temp = (const float*)d_in[14];
    const float* a2_q    = (const float*)d_in[15];
    const float* a2_qdw  = (const float*)d_in[16];
    const float* a2_kv   = (const float*)d_in[17];
    const float* a2_kvdw = (const float*)d_in[18];
    const float* a2_po   = (const float*)d_in[19];
    const float* a2_temp = (const float*)d_in[20];
    const float* conv1_w = (const float*)d_in[21];
    const float* ca1_w   = (const float*)d_in[22];
    const float* ca1_b   = (const float*)d_in[23];
    const float* ca2_w   = (const float*)d_in[24];
    const float* ca2_b   = (const float*)d_in[25];
    const float* ffn_pi  = (const float*)d_in[26];
    const float* ffn_dw  = (const float*)d_in[27];
    const float* ffn_po  = (const float*)d_in[28];
    float* out = (float*)d_out;

    float *bufCb, *bufCc, *bufCd, *bufCe, *buf2Ca, *buf2Cb, *buf2Cc, *bufHa, *bufHb, *xout;
    float *mu, *inv, *attnp, *attnw, *Mw, *pool, *cas;
    cudaGetSymbolAddress((void**)&bufCb, g_bufCb);
    cudaGetSymbolAddress((void**)&bufCc, g_bufCc);
    cudaGetSymbolAddress((void**)&bufCd, g_bufCd);
    cudaGetSymbolAddress((void**)&bufCe, g_bufCe);
    cudaGetSymbolAddress((void**)&buf2Ca, g_buf2Ca);
    cudaGetSymbolAddress((void**)&buf2Cb, g_buf2Cb);
    cudaGetSymbolAddress((void**)&buf2Cc, g_buf2Cc);
    cudaGetSymbolAddress((void**)&bufHa, g_bufHa);
    cudaGetSymbolAddress((void**)&bufHb, g_bufHb);
    cudaGetSymbolAddress((void**)&xout, g_xout);
    cudaGetSymbolAddress((void**)&mu, g_mu);
    cudaGetSymbolAddress((void**)&inv, g_inv);
    cudaGetSymbolAddress((void**)&attnp, g_attnp);
    cudaGetSymbolAddress((void**)&attnw, g_attnw);
    cudaGetSymbolAddress((void**)&Mw, g_Mw);
    cudaGetSymbolAddress((void**)&pool, g_pool);
    cudaGetSymbolAddress((void**)&cas, g_cas);

    dim3 tb(256);
    dim3 gLN2(N_ / 256, 2 * B_);
    dim3 gLN(N_ / 256, B_);
    dim3 gQ(N_ / 128, 1, 2 * B_);
    dim3 gKV(N_ / 128, 2, 2 * B_);
    dim3 gMv(N_ / 128, 1, 2 * B_);
    dim3 gG_C(N_ / 128, 1, B_);
    dim3 gG_H(N_ / 128, (HID2_ + 127) / 128, B_);
    dim3 gRow(C_, B_);
    dim3 gAttnP(NCHUNK_, HEADS_, 2 * B_);
    dim3 gAttnF(HEADS_, 2 * B_);
    dim3 gDWall(Hh_ / 8, C_ + C2_, 2 * B_);
    dim3 gDW_H(Hh_ / 8, HID_, B_);

    // ===== both attention paths, merged launches =====
    // q: path1 from high, path2 from low
    sgemm128<<<gQ, tb>>>(a1_q, high, bufCb, nullptr,
                         a2_q, low, bufCc, nullptr,
                         nullptr, nullptr, nullptr, nullptr, nullptr, nullptr,
                         C_, C_, C_, C_, 0, 0, 0, 0);
    lnstats2k<<<gLN2, tb>>>(low, high, mu, inv);
    // kv: path1 = a1_kv @ LN(low), path2 = a2_kv @ LN(high)
    sgemm128<<<gKV, tb>>>(a1_kv, low, buf2Ca, nullptr,
                          a2_kv, high, buf2Cb, nullptr,
                          mu, inv, norm1_w, norm1_b, norm_1_w, norm_1_b,
                          C2_, C_, C_, C2_, 0, 0, 4, 0);
    // all depthwise convs (q + kv, both paths)
    dwallk<<<gDWall, tb>>>(bufCb, bufCc, a1_qdw, a2_qdw, bufCd, bufCe,
                           buf2Ca, buf2Cb, a1_kvdw, a2_kvdw, buf2Cc, bufHa);
    attnpartk<<<gAttnP, tb>>>(bufCd, bufCe, buf2Cc, bufHa, attnp);
    attnfink<<<gAttnF, tb>>>(attnp, a1_temp, a2_temp, attnw);
    poattnk<<<dim3(2 * B_), tb>>>(a1_po, a2_po, attnw, Mw);
    // concat result: path1 -> buf2Ca[0:C] (+low), path2 -> buf2Ca[C:2C] (+high)
    sgemm128<<<gMv, tb>>>(Mw, buf2Cc + (size_t)C_ * N_, buf2Ca, low,
                          Mw + (size_t)B_ * C_ * C_, bufHa + (size_t)C_ * N_, buf2Ca, high,
                          nullptr, nullptr, nullptr, nullptr, nullptr, nullptr,
                          C_, C_, C2_, C2_, 0, C_, 1, C_ * C_);

    // ===== fuse: conv1(concat) -> CA -> + origin, fused with norm2 stats =====
    sgemm128<<<gG_C, tb>>>(conv1_w, buf2Ca, bufCb, nullptr,
                           conv1_w, buf2Ca, bufCb, nullptr,
                           nullptr, nullptr, nullptr, nullptr, nullptr, nullptr,
                           C_, C2_, C2_, C_, 0, 0, 0, 0);
    capoolk<<<gRow, tb>>>(bufCb, pool);
    cafck<<<dim3(B_), dim3(128)>>>(pool, ca1_w, ca1_b, ca2_w, ca2_b, cas);
    scaleaddstatsk<<<gLN, tb>>>(bufCb, cas, origin, xout, mu, inv);

    // ===== FFN with residual =====
    sgemm128<<<gG_H, tb>>>(ffn_pi, xout, bufHa, nullptr,
                           ffn_pi, xout, bufHa, nullptr,
                           mu, inv, norm2_w, norm2_b, norm2_w, norm2_b,
                           HID2_, C_, C_, HID2_, 0, 0, 4, 0);
    dwgatek<<<gDW_H, tb>>>(bufHa, ffn_dw, bufHb);
    sgemm128<<<gG_C, tb>>>(ffn_po, bufHb, out, xout,
                           ffn_po, bufHb, out, xout,
                           nullptr, nullptr, nullptr, nullptr, nullptr, nullptr,
                           C_, HID_, HID_, C_, 0, 0, 3, 0);
}

// round 10
// speedup vs baseline: 2.2770x; 1.3518x over previous
#include <cuda_runtime.h>
#include <cuda_bf16.h>
#include <math.h>
#include <stdint.h>

#define B_    8
#define C_    128
#define Hh_   128
#define Ww_   128
#define N_    16384      // H*W
#define HEADS_ 8
#define CH_   16         // C/HEADS
#define HID_  340
#define HID2_ 680
#define C2_   256
#define NCHUNK_ 16
#define CHUNKN_ (N_ / NCHUNK_)   // 1024

// ---------------- static scratch (no allocations allowed) ----------------
__device__ float g_bufCb[(size_t)B_ * C_ * N_];   // qpre path1 / conv1 out
__device__ float g_bufCc[(size_t)B_ * C_ * N_];   // qpre path2
__device__ float g_bufCd[(size_t)B_ * C_ * N_];   // qdw path1
__device__ float g_bufCe[(size_t)B_ * C_ * N_];   // qdw path2
__device__ float g_buf2Ca[(size_t)B_ * C2_ * N_]; // kvpre path1 / concat out
__device__ float g_buf2Cb[(size_t)B_ * C2_ * N_]; // kvpre path2
__device__ float g_buf2Cc[(size_t)B_ * C2_ * N_]; // kvdw path1
__device__ float g_bufHa[(size_t)B_ * HID2_ * N_];// kvdw path2 (front 2C) / ffn hidden
__device__ float g_bufHb[(size_t)B_ * HID_ * N_]; // gated
__device__ float g_xout[(size_t)B_ * C_ * N_];
__device__ float g_mu[2 * B_ * N_];
__device__ float g_inv[2 * B_ * N_];
__device__ float g_attnp[2 * B_ * HEADS_ * NCHUNK_ * 288];
__device__ float g_attnw[2 * B_ * HEADS_ * CH_ * CH_];
__device__ float g_Mw[2 * B_ * C_ * C_];
__device__ float g_pool[B_ * C_];
__device__ float g_cas[B_ * C_];

// packed f32x2 helpers (fallback path)
#define FMA2(d, a, b) asm("fma.rn.f32x2 %0, %1, %2, %0;" : "+l"(d) : "l"(a), "l"(b))
#define UNPK2(lo, hi, s) asm("mov.b64 {%0, %1}, %2;" : "=f"(lo), "=f"(hi) : "l"(s))

// ---------------- PTX helpers ----------------
__device__ __forceinline__ uint32_t smem_u32(const void* p) {
    uint32_t a;
    asm("{ .reg .u64 t; cvta.to.shared.u64 t, %1; cvt.u32.u64 %0, t; }" : "=r"(a) : "l"(p));
    return a;
}
#define SWZ(o) ((o) ^ (((o) >> 3) & 0x70))

#if defined(__CUDA_ARCH_FEAT_SM103_ALL) || !defined(__CUDA_ARCH__)
#define HAS_TC 1
#else
#define HAS_TC 0
#endif

#define MBARRIER_INIT(addr, cnt) \
    asm volatile("mbarrier.init.shared.b64 [%0], %1;" :: "r"((uint32_t)(addr)), "r"((uint32_t)(cnt)) : "memory")
#define MBARRIER_INVAL(addr) \
    asm volatile("mbarrier.inval.shared.b64 [%0];" :: "r"((uint32_t)(addr)) : "memory")
#define MBARRIER_WAIT_PARITY(mbar_smem_addr, phase_parity) do { \
    uint32_t _mbar = (uint32_t)(mbar_smem_addr); \
    uint32_t _parity = (uint32_t)(phase_parity); \
    uint32_t _done; \
    asm volatile("{\n\t.reg .pred p;\n\t" \
        "mbarrier.try_wait.parity.acquire.cta.shared::cta.b64 p, [%1], %2;\n\t" \
        "selp.b32 %0, 1, 0, p;\n\t}" : "=r"(_done) : "r"(_mbar), "r"(_parity) : "memory"); \
    if (!_done) { \
        asm volatile("{\n\t.reg .pred P1;\n\t" \
            "WAIT_LOOP_%=:\n\t" \
            "mbarrier.try_wait.parity.acquire.cta.shared::cta.b64 P1, [%0], %1, 0x989680;\n\t" \
            "@P1 bra.uni WAIT_DONE_%=;\n\t" \
            "bra.uni WAIT_LOOP_%=;\n\t" \
            "WAIT_DONE_%=:\n\t}" :: "r"(_mbar), "r"(_parity) : "memory"); \
    } \
} while (0)

#if HAS_TC
#define TCGEN05_ALLOC(smem_result_addr, nCols) \
    asm volatile("tcgen05.alloc.cta_group::1.sync.aligned.shared::cta.b32 [%0], %1;" \
        :: "r"((uint32_t)(smem_result_addr)), "r"((uint32_t)(nCols)) : "memory")
#define TCGEN05_DEALLOC(tmem_addr, nCols) \
    asm volatile("tcgen05.dealloc.cta_group::1.sync.aligned.b32 %0, %1;" :: "r"(tmem_addr), "r"((uint32_t)(nCols)))
#define TCGEN05_RELINQUISH() \
    asm volatile("tcgen05.relinquish_alloc_permit.cta_group::1.sync.aligned;")
#define TCGEN05_COMMIT(mbar_smem_addr) \
    asm volatile("tcgen05.commit.cta_group::1.mbarrier::arrive::one.shared::cluster.b64 [%0];" \
        :: "r"((uint32_t)(mbar_smem_addr)) : "memory")
#define TCGEN05_FENCE_AFTER() asm volatile("tcgen05.fence::after_thread_sync;" ::: "memory")
#define TCGEN05_FENCE_BEFORE() asm volatile("tcgen05.fence::before_thread_sync;" ::: "memory")
#define TCGEN05_WAIT_LD() asm volatile("tcgen05.wait::ld.sync.aligned;" ::: "memory")
#define FENCE_ASYNC_SHARED() asm volatile("fence.proxy.async.shared::cta;" ::: "memory")

#define TCGEN05_LD_32X32B_X32(r, tmem_addr) \
    asm volatile( \
        "tcgen05.ld.sync.aligned.32x32b.x32.b32 " \
        "{%0, %1, %2, %3, %4, %5, %6, %7, " \
        " %8, %9, %10, %11, %12, %13, %14, %15, " \
        " %16, %17, %18, %19, %20, %21, %22, %23, " \
        " %24, %25, %26, %27, %28, %29, %30, %31}, [%32];" \
        : "=r"((r)[0]),  "=r"((r)[1]),  "=r"((r)[2]),  "=r"((r)[3]), \
          "=r"((r)[4]),  "=r"((r)[5]),  "=r"((r)[6]),  "=r"((r)[7]), \
          "=r"((r)[8]),  "=r"((r)[9]),  "=r"((r)[10]), "=r"((r)[11]), \
          "=r"((r)[12]), "=r"((r)[13]), "=r"((r)[14]), "=r"((r)[15]), \
          "=r"((r)[16]), "=r"((r)[17]), "=r"((r)[18]), "=r"((r)[19]), \
          "=r"((r)[20]), "=r"((r)[21]), "=r"((r)[22]), "=r"((r)[23]), \
          "=r"((r)[24]), "=r"((r)[25]), "=r"((r)[26]), "=r"((r)[27]), \
          "=r"((r)[28]), "=r"((r)[29]), "=r"((r)[30]), "=r"((r)[31]) \
        : "r"(tmem_addr))

// SW128 SMEM descriptor (LBO=1, SBO=64, version=1, layout=SW128)
__device__ __forceinline__ uint64_t make_desc(uint32_t addr) {
    const uint64_t base = (uint64_t(2) << 61) | (uint64_t(1) << 46)
                        | (uint64_t(64) << 32) | (uint64_t(1) << 16);
    return base | ((uint64_t)(addr >> 4) & 0x3FFF);
}

// bf16 SS MMA, cg1: D[M=128, N=128] += A[M,K=16] * B[N,K=16]^T
#define MMA_IDESC 0x8200490u
__device__ __forceinline__ void mma_bf16_ss(uint32_t d, uint64_t ad, uint64_t bd, uint32_t en) {
    asm volatile(
        "{\n\t.reg .pred p;\n\tsetp.ne.u32 p, %5, 0;\n\t"
        "tcgen05.mma.cta_group::1.kind::f16 [%0], %1, %2, %3, {%4, %4, %4, %4}, p;\n\t}"
        :: "r"(d), "l"(ad), "l"(bd), "r"(MMA_IDESC), "r"(0u), "r"(en) : "memory");
}
#endif  // HAS_TC

// dynamic smem layout (bytes)
#define SM_TMEM   0
#define SM_MBAR   16           // 2 mbarriers @16, @24
#define SM_XS     64           // fp32 staging: 64 x 132 floats = 33792 B
#define SM_TILES  34816        // 1024-aligned; per buffer: AHI,ALO,BHI,BLO @16KB each
#define SM_BUFSZ  65536
#define SM_TOTAL  (SM_TILES + 2 * SM_BUFSZ)   // 165888 B

__device__ __forceinline__ void f2bf2(float x, uint16_t& h, uint16_t& l) {
    __nv_bfloat16 hb = __float2bfloat16_rn(x);
    __nv_bfloat16 lb = __float2bfloat16_rn(x - __bfloat162float(hb));
    h = __bfloat16_as_ushort(hb);
    l = __bfloat16_as_ushort(lb);
}

// ---------------- GEMM: Y[b, Yoff+o, p] = sum_c W[o,c] LN?(X[b,c,p]) ----------------
// flags: 1=residual add, 2=nan_to_num, 4=apply LN to X on load
__global__ void __launch_bounds__(256, 1)
gemmtc(const float* __restrict__ W1, const float* __restrict__ X1,
       float* __restrict__ Y1, const float* __restrict__ R1,
       const float* __restrict__ W2, const float* __restrict__ X2,
       float* __restrict__ Y2, const float* __restrict__ R2,
       const float* __restrict__ lnMu, const float* __restrict__ lnInv,
       const float* __restrict__ lnW1, const float* __restrict__ lnB1,
       const float* __restrict__ lnW2, const float* __restrict__ lnB2,
       int Cout, int Cin, int XCtot, int YCtot, int Yoff1, int Yoff2,
       int flags, int WstrideB)
{
    extern __shared__ __align__(1024) char smem[];

    const int bz = blockIdx.z;
    const int pth = bz >= B_;
    const int b = pth ? bz - B_ : bz;
    const int o0 = blockIdx.y * 128;
    const int p0 = blockIdx.x * 128;
    const float* Wb = (pth ? W2 : W1) + (size_t)b * WstrideB;
    const float* Xb = (pth ? X2 : X1) + (size_t)b * XCtot * N_;
    float* Y = pth ? Y2 : Y1;
    const float* R = pth ? R2 : R1;
    const float* lnW = pth ? lnW2 : lnW1;
    const float* lnB = pth ? lnB2 : lnB1;
    const int Yoff = pth ? Yoff2 : Yoff1;
    const int lnOn = flags & 4;
    const int tid = threadIdx.x;

#if HAS_TC && defined(__CUDA_ARCH__)
    // ================= tcgen05 path (sm_103a cubin) =================
    const uint32_t sb = smem_u32(smem);
    const int wid = tid >> 5;

    if (tid == 0) {
        MBARRIER_INIT(sb + SM_MBAR, 1);
        MBARRIER_INIT(sb + SM_MBAR + 8, 1);
    }
    if (wid == 0) TCGEN05_ALLOC(sb + SM_TMEM, 128);
    __syncthreads();
    uint32_t tmem;
    asm volatile("ld.shared.b32 %0, [%1];" : "=r"(tmem) : "r"(sb + SM_TMEM));

    const int nch = (Cin + 63) >> 6;
    int ph0 = 0, ph1 = 0;
    uint32_t en = 0;

    float* xs = (float*)(smem + SM_XS);

    for (int ch = 0; ch < nch; ++ch) {
        const int bf = ch & 1;
        const int k0 = ch << 6;
        if (ch >= 2) {
            if (bf == 0) { MBARRIER_WAIT_PARITY(sb + SM_MBAR, ph0); ph0 ^= 1; }
            else         { MBARRIER_WAIT_PARITY(sb + SM_MBAR + 8, ph1); ph1 ^= 1; }
        }
        char* abase = smem + SM_TILES + bf * SM_BUFSZ;
        char* albase = abase + 16384;
        char* bbase = abase + 32768;
        char* blbase = abase + 49152;

        // ---- stage A (W): 128 rows x 64 k, hi/lo bf16, SW128 ----
        {
            int r = tid >> 1;
            int kh = (tid & 1) << 5;
            int o = o0 + r;
            bool fast = (o < Cout) && (k0 + kh + 31 < Cin);
            #pragma unroll
            for (int i = 0; i < 8; ++i) {
                int kk = k0 + kh + i * 4;
                float4 v;
                if (fast) v = *(const float4*)&Wb[(size_t)o * Cin + kk];
                else {
                    v.x = (o < Cout && kk + 0 < Cin) ? Wb[(size_t)o * Cin + kk + 0] : 0.f;
                    v.y = (o < Cout && kk + 1 < Cin) ? Wb[(size_t)o * Cin + kk + 1] : 0.f;
                    v.z = (o < Cout && kk + 2 < Cin) ? Wb[(size_t)o * Cin + kk + 2] : 0.f;
                    v.w = (o < Cout && kk + 3 < Cin) ? Wb[(size_t)o * Cin + kk + 3] : 0.f;
                }
                uint16_t h0, l0, h1, l1, h2, l2, h3, l3;
                f2bf2(v.x, h0, l0); f2bf2(v.y, h1, l1);
                f2bf2(v.z, h2, l2); f2bf2(v.w, h3, l3);
                uint2 hw = make_uint2((uint32_t)h0 | ((uint32_t)h1 << 16),
                                      (uint32_t)h2 | ((uint32_t)h3 << 16));
                uint2 lw = make_uint2((uint32_t)l0 | ((uint32_t)l1 << 16),
                                      (uint32_t)l2 | ((uint32_t)l3 << 16));
                uint32_t off = SWZ((uint32_t)(r * 128 + (kh + i * 4) * 2));
                *(uint2*)(abase + off) = hw;
                *(uint2*)(albase + off) = lw;
            }
        }

        // ---- stage B phase 1: X [64 k][128 p] fp32 -> Xs (LN applied) ----
        {
            int kr = tid >> 2;
            int pc = (tid & 3) << 5;
            int kk = k0 + kr;
            float* xrow = xs + kr * 132 + pc;
            if (kk < Cin) {
                const float* src = Xb + (size_t)kk * N_ + p0 + pc;
                if (lnOn) {
                    float wv = lnW[kk], bv = lnB[kk];
                    #pragma unroll
                    for (int i = 0; i < 8; ++i) {
                        float4 v = *(const float4*)&src[i * 4];
                        float4 m  = *(const float4*)&lnMu[(size_t)bz * N_ + p0 + pc + i * 4];
                        float4 iv = *(const float4*)&lnInv[(size_t)bz * N_ + p0 + pc + i * 4];
                        v.x = (v.x - m.x) * iv.x * wv + bv;
                        v.y = (v.y - m.y) * iv.y * wv + bv;
                        v.z = (v.z - m.z) * iv.z * wv + bv;
                        v.w = (v.w - m.w) * iv.w * wv + bv;
                        *(float4*)&xrow[i * 4] = v;
                    }
                } else {
                    #pragma unroll
                    for (int i = 0; i < 8; ++i)
                        *(float4*)&xrow[i * 4] = *(const float4*)&src[i * 4];
                }
            } else {
                #pragma unroll
                for (int i = 0; i < 8; ++i)
                    *(float4*)&xrow[i * 4] = make_float4(0.f, 0.f, 0.f, 0.f);
            }
        }
        __syncthreads();

        // ---- stage B phase 2: transpose + convert -> B[n][k] hi/lo bf16 SW128 ----
        {
            int n = tid & 127;
            int half = tid >> 7;
            #pragma unroll
            for (int g = 0; g < 4; ++g) {
                uint32_t hw[4], lw[4];
                #pragma unroll
                for (int q = 0; q < 4; ++q) {
                    int k1 = half * 32 + g * 8 + q * 2;
                    uint16_t h0, l0, h1, l1;
                    f2bf2(xs[(k1 + 0) * 132 + n], h0, l0);
                    f2bf2(xs[(k1 + 1) * 132 + n], h1, l1);
                    hw[q] = (uint32_t)h0 | ((uint32_t)h1 << 16);
                    lw[q] = (uint32_t)l0 | ((uint32_t)l1 << 16);
                }
                uint32_t off = SWZ((uint32_t)(n * 128 + half * 64 + g * 16));
                *(uint4*)(bbase + off) = make_uint4(hw[0], hw[1], hw[2], hw[3]);
                *(uint4*)(blbase + off) = make_uint4(lw[0], lw[1], lw[2], lw[3]);
            }
        }
        FENCE_ASYNC_SHARED();
        __syncthreads();

        // ---- issue MMAs for this chunk ----
        if (tid == 0) {
            uint64_t ah = make_desc(sb + SM_TILES + bf * SM_BUFSZ);
            uint64_t al = ah + (16384 >> 4);
            uint64_t bh = ah + (32768 >> 4);
            uint64_t bl = ah + (49152 >> 4);
            #pragma unroll
            for (int s = 0; s < 4; ++s) {
                uint64_t ofs = s * 2;
                mma_bf16_ss(tmem, ah + ofs, bh + ofs, en); en = 1;
                mma_bf16_ss(tmem, ah + ofs, bl + ofs, 1);
                mma_bf16_ss(tmem, al + ofs, bh + ofs, 1);
            }
            TCGEN05_COMMIT(sb + SM_MBAR + bf * 8);
        }
    }

    // ---- drain ----
    { MBARRIER_WAIT_PARITY(sb + SM_MBAR, ph0); }
    if (nch >= 2) { MBARRIER_WAIT_PARITY(sb + SM_MBAR + 8, ph1); }
    TCGEN05_FENCE_AFTER();

    // ---- epilogue: warps 0-3 read TMEM D and store ----
    const int doResid = flags & 1, doFinal = flags & 2;
    if (tid < 128) {
        int w = tid >> 5, l = tid & 31;
        int o = o0 + w * 32 + l;
        #pragma unroll
        for (int g = 0; g < 4; ++g) {
            uint32_t dr[32];
            TCGEN05_LD_32X32B_X32(dr, tmem + g * 32);
            TCGEN05_WAIT_LD();
            if (o < Cout) {
                size_t ybase = ((size_t)b * YCtot + Yoff + o) * N_ + p0 + g * 32;
                size_t rbase = ((size_t)b * Cout + o) * N_ + p0 + g * 32;
                #pragma unroll
                for (int q = 0; q < 8; ++q) {
                    float v0 = __uint_as_float(dr[q * 4 + 0]);
                    float v1 = __uint_as_float(dr[q * 4 + 1]);
                    float v2 = __uint_as_float(dr[q * 4 + 2]);
                    float v3 = __uint_as_float(dr[q * 4 + 3]);
                    if (doResid) {
                        float4 r4 = *(const float4*)&R[rbase + q * 4];
                        v0 += r4.x; v1 += r4.y; v2 += r4.z; v3 += r4.w;
                    }
                    if (doFinal) {
                        v0 = isfinite(v0) ? v0 : 1e-5f;
                        v1 = isfinite(v1) ? v1 : 1e-5f;
                        v2 = isfinite(v2) ? v2 : 1e-5f;
                        v3 = isfinite(v3) ? v3 : 1e-5f;
                    }
                    *(float4*)&Y[ybase + q * 4] = make_float4(v0, v1, v2, v3);
                }
            }
        }
        TCGEN05_FENCE_BEFORE();
    }

    __syncthreads();
    if (tid == 0) { MBARRIER_INVAL(sb + SM_MBAR); MBARRIER_INVAL(sb + SM_MBAR + 8); }
    __syncthreads();
    if (wid == 0) {
        TCGEN05_RELINQUISH();
        TCGEN05_DEALLOC(tmem, 128);
    }
#else
    // ================= FFMA2 fallback (compute_103 PTX pass) =================
    float2 (*Ws2)[16][128] = (float2(*)[16][128])(smem);            // 32KB
    float  (*Xs)[16][128]  = (float(*)[16][128])(smem + 32768);     // 16KB

    const int tx = tid & 15, ty = tid >> 4;
    unsigned long long acc2[8][4];
    #pragma unroll
    for (int i = 0; i < 8; ++i)
        #pragma unroll
        for (int j = 0; j < 4; ++j) acc2[i][j] = 0ULL;

    const int ktiles = (Cin + 15) >> 4;
    for (int kt = 0; kt < ktiles; ++kt) {
        int buf = kt & 1;
        int k0 = kt * 16;
        #pragma unroll
        for (int u = 0; u < 2; ++u) {
            int e4 = tid + 256 * u;
            int row = e4 & 127, kq = e4 >> 7;
            int o = o0 + row;
            #pragma unroll
            for (int t = 0; t < 4; ++t) {
                int kk = k0 + kq * 4 + t;
                float w = (o < Cout && kk < Cin) ? Wb[(size_t)o * Cin + kk] : 0.f;
                Ws2[buf][kq * 4 + t][row] = make_float2(w, w);
            }
        }
        #pragma unroll
        for (int u = 0; u < 2; ++u) {
            int e = tid + 256 * u;
            int row = e >> 5, cq = e & 31;
            int kk = k0 + row;
            float4 v = (kk < Cin) ? *(const float4*)&Xb[(size_t)kk * N_ + p0 + cq * 4]
                                  : make_float4(0.f, 0.f, 0.f, 0.f);
            if (lnOn && kk < Cin) {
                int pix = p0 + cq * 4;
                float4 m  = *(const float4*)&lnMu[(size_t)bz * N_ + pix];
                float4 iv = *(const float4*)&lnInv[(size_t)bz * N_ + pix];
                float wv = lnW[kk], bv = lnB[kk];
                v.x = (v.x - m.x) * iv.x * wv + bv;
                v.y = (v.y - m.y) * iv.y * wv + bv;
                v.z = (v.z - m.z) * iv.z * wv + bv;
                v.w = (v.w - m.w) * iv.w * wv + bv;
            }
            *(float4*)&Xs[buf][row][cq * 4] = v;
        }
        __syncthreads();
        #pragma unroll
        for (int k = 0; k < 16; ++k) {
            ulonglong2 q0 = *(const ulonglong2*)&Xs[buf][k][tx * 4];
            ulonglong2 q1 = *(const ulonglong2*)&Xs[buf][k][64 + tx * 4];
            unsigned long long bb0 = q0.x, bb1 = q0.y, bb2 = q1.x, bb3 = q1.y;
            const ulonglong2* wrow = (const ulonglong2*)&Ws2[buf][k][ty * 8];
            ulonglong2 w01 = wrow[0], w23 = wrow[1], w45 = wrow[2], w67 = wrow[3];
            unsigned long long av[8] = {w01.x, w01.y, w23.x, w23.y,
                                        w45.x, w45.y, w67.x, w67.y};
            #pragma unroll
            for (int i = 0; i < 8; ++i) {
                FMA2(acc2[i][0], av[i], bb0);
                FMA2(acc2[i][1], av[i], bb1);
                FMA2(acc2[i][2], av[i], bb2);
                FMA2(acc2[i][3], av[i], bb3);
            }
        }
        __syncthreads();
    }

    const int doResid = flags & 1, doFinal = flags & 2;
    #pragma unroll
    for (int i = 0; i < 8; ++i) {
        int o = o0 + ty * 8 + i;
        if (o >= Cout) continue;
        size_t ybase0 = ((size_t)b * YCtot + Yoff + o) * N_ + p0 + tx * 4;
        float v[8];
        #pragma unroll
        for (int j = 0; j < 4; ++j) UNPK2(v[2 * j], v[2 * j + 1], acc2[i][j]);
        if (doResid) {
            size_t rbase = ((size_t)b * Cout + o) * N_ + p0 + tx * 4;
            float4 r0 = *(const float4*)&R[rbase];
            float4 r1 = *(const float4*)&R[rbase + 64];
            v[0] += r0.x; v[1] += r0.y; v[2] += r0.z; v[3] += r0.w;
            v[4] += r1.x; v[5] += r1.y; v[6] += r1.z; v[7] += r1.w;
        }
        if (doFinal) {
            #pragma unroll
            for (int j = 0; j < 8; ++j) v[j] = isfinite(v[j]) ? v[j] : 1e-5f;
        }
        *(float4*)&Y[ybase0]      = make_float4(v[0], v[1], v[2], v[3]);
        *(float4*)&Y[ybase0 + 64] = make_float4(v[4], v[5], v[6], v[7]);
    }
#endif
}

// ---------------- per-pixel LN stats, both paths in one launch ----------------
__global__ void lnstats2k(const float* __restrict__ X1, const float* __restrict__ X2,
                          float* __restrict__ mu, float* __restrict__ inv)
{
    int p = blockIdx.x * 256 + threadIdx.x;
    int zc = blockIdx.y;
    int pth = zc >= B_;
    int b = pth ? zc - B_ : zc;
    const float* xb = (pth ? X2 : X1) + (size_t)b * C_ * N_ + p;
    float s = 0.f, ss = 0.f;
    #pragma unroll 4
    for (int c = 0; c < C_; ++c) {
        float v = xb[(size_t)c * N_];
        s += v; ss += v * v;
    }
    float m = s * (1.f / C_);
    float var = ss * (1.f / C_) - m * m;
    mu[(size_t)zc * N_ + p] = m;
    inv[(size_t)zc * N_ + p] = rsqrtf(var + 1e-5f);
}

// ---------------- fused: x_out = fuse*ca + origin ; write x_out + LN stats ----------------
__global__ void scaleaddstatsk(const float* __restrict__ fuse, const float* __restrict__ cas,
                               const float* __restrict__ origin, float* __restrict__ Y,
                               float* __restrict__ mu, float* __restrict__ inv)
{
    int p = blockIdx.x * 256 + threadIdx.x;
    int b = blockIdx.y;
    __shared__ float sc[C_];
    for (int i = threadIdx.x; i < C_; i += 256) sc[i] = cas[b * C_ + i];
    __syncthreads();
    const size_t base = (size_t)b * C_ * N_ + p;
    float s = 0.f, ss = 0.f;
    #pragma unroll 4
    for (int c = 0; c < C_; ++c) {
        float v = fuse[base + (size_t)c * N_] * sc[c] + origin[base + (size_t)c * N_];
        Y[base + (size_t)c * N_] = v;
        s += v; ss += v * v;
    }
    float m = s * (1.f / C_);
    float var = ss * (1.f / C_) - m * m;
    mu[b * N_ + p] = m;
    inv[b * N_ + p] = rsqrtf(var + 1e-5f);
}

// ---------------- ALL depthwise 3x3 for both paths (q: C ch, kv: 2C ch) ----------------
__global__ void dwallk(const float* __restrict__ qX1, const float* __restrict__ qX2,
                       const float* __restrict__ qW1, const float* __restrict__ qW2,
                       float* __restrict__ qY1, float* __restrict__ qY2,
                       const float* __restrict__ kX1, const float* __restrict__ kX2,
                       const float* __restrict__ kW1, const float* __restrict__ kW2,
                       float* __restrict__ kY1, float* __restrict__ kY2)
{
    int cidx = blockIdx.y;
    int zc = blockIdx.z;
    int pth = zc >= B_;
    int b = pth ? zc - B_ : zc;
    const float* xb; const float* Wd; float* yb; int c;
    if (cidx < C_) {
        c = cidx;
        xb = (pth ? qX2 : qX1) + ((size_t)b * C_ + c) * N_;
        Wd = (pth ? qW2 : qW1);
        yb = (pth ? qY2 : qY1) + ((size_t)b * C_ + c) * N_;
    } else {
        c = cidx - C_;
        xb = (pth ? kX2 : kX1) + ((size_t)b * C2_ + c) * N_;
        Wd = (pth ? kW2 : kW1);
        yb = (pth ? kY2 : kY1) + ((size_t)b * C2_ + c) * N_;
    }
    int y0 = blockIdx.x * 8;
    int tid = threadIdx.x;
    __shared__ float t[10][128];
    for (int i = tid; i < 320; i += 256) {
        int r = i >> 5, xq = i & 31;
        int yy = y0 - 1 + r;
        float4 v = make_float4(0.f, 0.f, 0.f, 0.f);
        if (yy >= 0 && yy < Hh_) v = *(const float4*)&xb[yy * 128 + xq * 4];
        *(float4*)&t[r][xq * 4] = v;
    }
    float w[9];
    #pragma unroll
    for (int q = 0; q < 9; ++q) w[q] = Wd[c * 9 + q];
    __syncthreads();
    int r = tid >> 5;
    int lx = tid & 31;
    float* yo = yb + (y0 + r) * 128;
    #pragma unroll
    for (int u = 0; u < 4; ++u) {
        int x = u * 32 + lx;
        float s = 0.f;
        #pragma unroll
        for (int dy = 0; dy < 3; ++dy) {
            const float* row = t[r + dy];
            float m  = row[x];
            float l  = (x > 0)   ? row[x - 1] : 0.f;
            float rr = (x < 127) ? row[x + 1] : 0.f;
            s += l * w[dy * 3] + m * w[dy * 3 + 1] + rr * w[dy * 3 + 2];
        }
        yo[x] = s;
    }
}

// ---------------- fused FFN dwconv(680) + gelu-gate -> 340 (smem-tiled) ----------------
__global__ void dwgatek(const float* __restrict__ X, const float* __restrict__ Wd,
                        float* __restrict__ Y)
{
    int c = blockIdx.y, b = blockIdx.z;
    int y0 = blockIdx.x * 8;
    int tid = threadIdx.x;
    const float* x1b = X + ((size_t)b * HID2_ + c) * N_;
    const float* x2b = X + ((size_t)b * HID2_ + c + HID_) * N_;
    __shared__ float t1[10][128];
    __shared__ float t2[10][128];
    for (int i = tid; i < 320; i += 256) {
        int r = i >> 5, xq = i & 31;
        int yy = y0 - 1 + r;
        float4 v1 = make_float4(0.f, 0.f, 0.f, 0.f);
        float4 v2 = v1;
        if (yy >= 0 && yy < Hh_) {
            v1 = *(const float4*)&x1b[yy * 128 + xq * 4];
            v2 = *(const float4*)&x2b[yy * 128 + xq * 4];
        }
        *(float4*)&t1[r][xq * 4] = v1;
        *(float4*)&t2[r][xq * 4] = v2;
    }
    float w1[9], w2[9];
    #pragma unroll
    for (int q = 0; q < 9; ++q) { w1[q] = Wd[c * 9 + q]; w2[q] = Wd[(c + HID_) * 9 + q]; }
    __syncthreads();
    int r = tid >> 5;
    int lx = tid & 31;
    float* yo = Y + ((size_t)b * HID_ + c) * N_ + (y0 + r) * 128;
    #pragma unroll
    for (int u = 0; u < 4; ++u) {
        int x = u * 32 + lx;
        float s1 = 0.f, s2 = 0.f;
        #pragma unroll
        for (int dy = 0; dy < 3; ++dy) {
            const float* r1 = t1[r + dy];
            const float* r2 = t2[r + dy];
            float m1  = r1[x],  m2  = r2[x];
            float l1  = (x > 0)   ? r1[x - 1] : 0.f;
            float l2  = (x > 0)   ? r2[x - 1] : 0.f;
            float rr1 = (x < 127) ? r1[x + 1] : 0.f;
            float rr2 = (x < 127) ? r2[x + 1] : 0.f;
            s1 += l1 * w1[dy * 3] + m1 * w1[dy * 3 + 1] + rr1 * w1[dy * 3 + 2];
            s2 += l2 * w2[dy * 3] + m2 * w2[dy * 3 + 1] + rr2 * w2[dy * 3 + 2];
        }
        float ge = 0.5f * s1 * (1.f + erff(s1 * 0.70710678118654752f));
        yo[x] = ge * s2;
    }
}

// ---------------- attention partials, both paths ----------------
__global__ void attnpartk(const float* __restrict__ Q1, const float* __restrict__ Q2,
                          const float* __restrict__ KV1, const float* __restrict__ KV2,
                          float* __restrict__ part)
{
    int chunk = blockIdx.x, h = blockIdx.y;
    int zc = blockIdx.z;
    int pth = zc >= B_;
    int b = pth ? zc - B_ : zc;
    const float* qb = (pth ? Q2 : Q1)  + ((size_t)b * C_  + h * CH_) * N_;
    const float* kb = (pth ? KV2 : KV1) + ((size_t)b * C2_ + h * CH_) * N_;

    __shared__ float sm[16 * 16 * 16];
    __shared__ float qqp[256], kkp[256];
    float* qs = sm;
    float* ks = sm + 1024;

    int tid = threadIdx.x;
    int i = tid & 15, s = tid >> 4;
    float acc[16];
    #pragma unroll
    for (int j = 0; j < 16; ++j) acc[j] = 0.f;
    float qq = 0.f, kk = 0.f;

    int nbeg = chunk * CHUNKN_;
    for (int n0 = nbeg; n0 < nbeg + CHUNKN_; n0 += 64) {
        #pragma unroll
        for (int u = 0; u < 4; ++u) {
            int e = tid + 256 * u;
            int r = e >> 6, cc = e & 63;
            qs[r * 64 + cc] = qb[(size_t)r * N_ + n0 + cc];
            ks[r * 64 + cc] = kb[(size_t)r * N_ + n0 + cc];
        }
        __syncthreads();
        #pragma unroll
        for (int t = 0; t < 4; ++t) {
            float qv = qs[i * 64 + s * 4 + t];
            float kv = ks[i * 64 + s * 4 + t];
            qq += qv * qv;
            kk += kv * kv;
            #pragma unroll
            for (int j = 0; j < 16; ++j) acc[j] += qv * ks[j * 64 + s * 4 + t];
        }
        __syncthreads();
    }
    qqp[s * 16 + i] = qq;
    kkp[s * 16 + i] = kk;
    #pragma unroll
    for (int j = 0; j < 16; ++j) sm[s * 256 + i * 16 + j] = acc[j];
    __syncthreads();

    float* pb = part + (((size_t)zc * HEADS_ + h) * NCHUNK_ + chunk) * 288;
    int i2 = tid >> 4, j2 = tid & 15;
    float a = 0.f;
    #pragma unroll
    for (int s2 = 0; s2 < 16; ++s2) a += sm[s2 * 256 + i2 * 16 + j2];
    pb[i2 * 16 + j2] = a;
    if (tid < 16) {
        float t0 = 0.f;
        #pragma unroll
        for (int s2 = 0; s2 < 16; ++s2) t0 += qqp[s2 * 16 + tid];
        pb[256 + tid] = t0;
    } else if (tid < 32) {
        int j = tid - 16;
        float t0 = 0.f;
        #pragma unroll
        for (int s2 = 0; s2 < 16; ++s2) t0 += kkp[s2 * 16 + j];
        pb[272 + j] = t0;
    }
}

// ---------------- attention finalize, both paths ----------------
__global__ void attnfink(const float* __restrict__ part, const float* __restrict__ temp1,
                         const float* __restrict__ temp2, float* __restrict__ attnOut)
{
    int h = blockIdx.x;
    int zc = blockIdx.y;
    int pth = zc >= B_;
    const float* temp = pth ? temp2 : temp1;
    const float* pb = part + ((size_t)zc * HEADS_ + h) * NCHUNK_ * 288;
    __shared__ float qqs[16], kks[16];
    int tid = threadIdx.x;

    float a = 0.f;
    #pragma unroll
    for (int c = 0; c < NCHUNK_; ++c) a += pb[c * 288 + tid];

    if (tid < 16) {
        float t0 = 0.f;
        #pragma unroll
        for (int c = 0; c < NCHUNK_; ++c) t0 += pb[c * 288 + 256 + tid];
        qqs[tid] = fmaxf(sqrtf(t0), 1e-12f);
    } else if (tid < 32) {
        int j = tid - 16;
        float t0 = 0.f;
        #pragma unroll
        for (int c = 0; c < NCHUNK_; ++c) t0 += pb[c * 288 + 272 + j];
        kks[j] = fmaxf(sqrtf(t0), 1e-12f);
    }
    __syncthreads();

    int i2 = tid >> 4, j2 = tid & 15;
    a = a / (qqs[i2] * kks[j2]) * temp[h];

    unsigned mask = 0xFFFFFFFFu;
    float mx = a;
    for (int w = 8; w > 0; w >>= 1) mx = fmaxf(mx, __shfl_xor_sync(mask, mx, w, 16));
    float e = expf(a - mx);
    float ssum = e;
    for (int w = 8; w > 0; w >>= 1) ssum += __shfl_xor_sync(mask, ssum, w, 16);
    attnOut[((size_t)zc * HEADS_ + h) * 256 + i2 * 16 + j2] = e / ssum;
}

// ---------------- M[zc] = po @ blockdiag(attn[zc]) : [C_, C_], both paths ----------------
__global__ void poattnk(const float* __restrict__ po1, const float* __restrict__ po2,
                        const float* __restrict__ attn, float* __restrict__ M)
{
    int zc = blockIdx.x;
    const float* po = (zc >= B_) ? po2 : po1;
    __shared__ float at[HEADS_ * 256];
    for (int i = threadIdx.x; i < HEADS_ * 256; i += 256)
        at[i] = attn[(size_t)zc * HEADS_ * 256 + i];
    __syncthreads();
    for (int idx = threadIdx.x; idx < C_ * C_; idx += 256) {
        int o = idx >> 7, cj = idx & 127;
        int h = cj >> 4, j = cj & 15;
        float s = 0.f;
        #pragma unroll
        for (int i = 0; i < 16; ++i) s += po[o * C_ + h * 16 + i] * at[h * 256 + i * 16 + j];
        M[((size_t)zc * C_ + o) * C_ + cj] = s;
    }
}

// ---------------- global average pool per (b,c) ----------------
__global__ void capoolk(const float* __restrict__ X, float* __restrict__ pool)
{
    int c = blockIdx.x, b = blockIdx.y;
    const float* xb = X + ((size_t)b * C_ + c) * N_;
    float s = 0.f;
    for (int n = threadIdx.x * 4; n < N_; n += 1024) {
        float4 v = *(const float4*)&xb[n];
        s += v.x + v.y + v.z + v.w;
    }
    __shared__ float red[256];
    red[threadIdx.x] = s; __syncthreads();
    for (int st = 128; st > 0; st >>= 1) {
        if (threadIdx.x < st) red[threadIdx.x] += red[threadIdx.x + st];
        __syncthreads();
    }
    if (threadIdx.x == 0) pool[b * C_ + c] = red[0] * (1.f / N_);
}

// ---------------- CA: relu FC (128->8) + sigmoid FC (8->128) ----------------
__global__ void cafck(const float* __restrict__ pool,
                      const float* __restrict__ w1, const float* __restrict__ b1,
                      const float* __restrict__ w2, const float* __restrict__ b2,
                      float* __restrict__ cas)
{
    int b = blockIdx.x, t = threadIdx.x;
    __shared__ float pl[C_];
    __shared__ float hid[8];
    pl[t] = pool[b * C_ + t];
    __syncthreads();
    if (t < 8) {
        float s = b1[t];
        #pragma unroll 4
        for (int c = 0; c < C_; ++c) s += w1[t * C_ + c] * pl[c];
        hid[t] = fmaxf(s, 0.f);
    }
    __syncthreads();
    float s = b2[t];
    #pragma unroll
    for (int r = 0; r < 8; ++r) s += w2[t * 8 + r] * hid[r];
    cas[b * C_ + t] = 1.f / (1.f + expf(-s));
}

// ---------------- host ----------------
extern "C" void kernel_launch(void* const* d_in, const int* in_sizes, int n_in,
                              void* d_out, int out_size)
{
    (void)in_sizes; (void)n_in; (void)out_size;
    const float* origin  = (const float*)d_in[0];
    const float* low     = (const float*)d_in[1];
    const float* high    = (const float*)d_in[2];
    const float* norm1_w = (const float*)d_in[3];
    const float* norm1_b = (const float*)d_in[4];
    const float* norm_1_w= (const float*)d_in[5];
    const float* norm_1_b= (const float*)d_in[6];
    const float* norm2_w = (const float*)d_in[7];
    const float* norm2_b = (const float*)d_in[8];
    const float* a1_q    = (const float*)d_in[9];
    const float* a1_qdw  = (const float*)d_in[10];
    const float* a1_kv   = (const float*)d_in[11];
    const float* a1_kvdw = (const float*)d_in[12];
    const float* a1_po   = (const float*)d_in[13];
    const float* a1_temp = (const float*)d_in[14];
    const float* a2_q    = (const float*)d_in[15];
    const float* a2_qdw  = (const float*)d_in[16];
    const float* a2_kv   = (const float*)d_in[17];
    const float* a2_kvdw = (const float*)d_in[18];
    const float* a2_po   = (const float*)d_in[19];
    const float* a2_temp = (const float*)d_in[20];
    const float* conv1_w = (const float*)d_in[21];
    const float* ca1_w   = (const float*)d_in[22];
    const float* ca1_b   = (const float*)d_in[23];
    const float* ca2_w   = (const float*)d_in[24];
    const float* ca2_b   = (const float*)d_in[25];
    const float* ffn_pi  = (const float*)d_in[26];
    const float* ffn_dw  = (const float*)d_in[27];
    const float* ffn_po  = (const float*)d_in[28];
    float* out = (float*)d_out;

    float *bufCb, *bufCc, *bufCd, *bufCe, *buf2Ca, *buf2Cb, *buf2Cc, *bufHa, *bufHb, *xout;
    float *mu, *inv, *attnp, *attnw, *Mw, *pool, *cas;
    cudaGetSymbolAddress((void**)&bufCb, g_bufCb);
    cudaGetSymbolAddress((void**)&bufCc, g_bufCc);
    cudaGetSymbolAddress((void**)&bufCd, g_bufCd);
    cudaGetSymbolAddress((void**)&bufCe, g_bufCe);
    cudaGetSymbolAddress((void**)&buf2Ca, g_buf2Ca);
    cudaGetSymbolAddress((void**)&buf2Cb, g_buf2Cb);
    cudaGetSymbolAddress((void**)&buf2Cc, g_buf2Cc);
    cudaGetSymbolAddress((void**)&bufHa, g_bufHa);
    cudaGetSymbolAddress((void**)&bufHb, g_bufHb);
    cudaGetSymbolAddress((void**)&xout, g_xout);
    cudaGetSymbolAddress((void**)&mu, g_mu);
    cudaGetSymbolAddress((void**)&inv, g_inv);
    cudaGetSymbolAddress((void**)&attnp, g_attnp);
    cudaGetSymbolAddress((void**)&attnw, g_attnw);
    cudaGetSymbolAddress((void**)&Mw, g_Mw);
    cudaGetSymbolAddress((void**)&pool, g_pool);
    cudaGetSymbolAddress((void**)&cas, g_cas);

    static int smem_set = 0;
    if (!smem_set) {
        cudaFuncSetAttribute(gemmtc, cudaFuncAttributeMaxDynamicSharedMemorySize, SM_TOTAL);
        smem_set = 1;
    }

    dim3 tb(256);
    dim3 gLN2(N_ / 256, 2 * B_);
    dim3 gLN(N_ / 256, B_);
    dim3 gQ(N_ / 128, 1, 2 * B_);
    dim3 gKV(N_ / 128, 2, 2 * B_);
    dim3 gMv(N_ / 128, 1, 2 * B_);
    dim3 gG_C(N_ / 128, 1, B_);
    dim3 gG_H(N_ / 128, (HID2_ + 127) / 128, B_);
    dim3 gRow(C_, B_);
    dim3 gAttnP(NCHUNK_, HEADS_, 2 * B_);
    dim3 gAttnF(HEADS_, 2 * B_);
    dim3 gDWall(Hh_ / 8, C_ + C2_, 2 * B_);
    dim3 gDW_H(Hh_ / 8, HID_, B_);

    // ===== both attention paths, merged launches =====
    gemmtc<<<gQ, tb, SM_TOTAL>>>(a1_q, high, bufCb, nullptr,
                                 a2_q, low, bufCc, nullptr,
                                 nullptr, nullptr, nullptr, nullptr, nullptr, nullptr,
                                 C_, C_, C_, C_, 0, 0, 0, 0);
    lnstats2k<<<gLN2, tb>>>(low, high, mu, inv);
    gemmtc<<<gKV, tb, SM_TOTAL>>>(a1_kv, low, buf2Ca, nullptr,
                                  a2_kv, high, buf2Cb, nullptr,
                                  mu, inv, norm1_w, norm1_b, norm_1_w, norm_1_b,
                                  C2_, C_, C_, C2_, 0, 0, 4, 0);
    dwallk<<<gDWall, tb>>>(bufCb, bufCc, a1_qdw, a2_qdw, bufCd, bufCe,
                           buf2Ca, buf2Cb, a1_kvdw, a2_kvdw, buf2Cc, bufHa);
    attnpartk<<<gAttnP, tb>>>(bufCd, bufCe, buf2Cc, bufHa, attnp);
    attnfink<<<gAttnF, tb>>>(attnp, a1_temp, a2_temp, attnw);
    poattnk<<<dim3(2 * B_), tb>>>(a1_po, a2_po, attnw, Mw);
    gemmtc<<<gMv, tb, SM_TOTAL>>>(Mw, buf2Cc + (size_t)C_ * N_, buf2Ca, low,
                                  Mw + (size_t)B_ * C_ * C_, bufHa + (size_t)C_ * N_, buf2Ca, high,
                                  nullptr, nullptr, nullptr, nullptr, nullptr, nullptr,
                                  C_, C_, C2_, C2_, 0, C_, 1, C_ * C_);

    // ===== fuse: conv1(concat) -> CA -> + origin, fused with norm2 stats =====
    gemmtc<<<gG_C, tb, SM_TOTAL>>>(conv1_w, buf2Ca, bufCb, nullptr,
                                   conv1_w, buf2Ca, bufCb, nullptr,
                                   nullptr, nullptr, nullptr, nullptr, nullptr, nullptr,
                                   C_, C2_, C2_, C_, 0, 0, 0, 0);
    capoolk<<<gRow, tb>>>(bufCb, pool);
    cafck<<<dim3(B_), dim3(128)>>>(pool, ca1_w, ca1_b, ca2_w, ca2_b, cas);
    scaleaddstatsk<<<gLN, tb>>>(bufCb, cas, origin, xout, mu, inv);

    // ===== FFN with residual =====
    gemmtc<<<gG_H, tb, SM_TOTAL>>>(ffn_pi, xout, bufHa, nullptr,
                                   ffn_pi, xout, bufHa, nullptr,
                                   mu, inv, norm2_w, norm2_b, norm2_w, norm2_b,
                                   HID2_, C_, C_, HID2_, 0, 0, 4, 0);
    dwgatek<<<gDW_H, tb>>>(bufHa, ffn_dw, bufHb);
    gemmtc<<<gG_C, tb, SM_TOTAL>>>(ffn_po, bufHb, out, xout,
                                   ffn_po, bufHb, out, xout,
                                   nullptr, nullptr, nullptr, nullptr, nullptr, nullptr,
                                   C_, HID_, HID_, C_, 0, 0, 3, 0);
}